// round 4
// baseline (speedup 1.0000x reference)
#include <cuda_runtime.h>

typedef unsigned long long ull;

#define DI 64
#define BR 128
#define BC 64

struct __align__(16) Smem {
    float ps[BR * 64];    // x -> p -> normalized agg   (row-major [r][d], no swizzle)
    float at[BR * 64];    // attn [r][j] row-major (no swizzle; GEMM2 a-loads broadcast)
    float nbr[BC * 64];   // nb tile row-major [j][d], d-quads swizzled by (j>>2)&7
    float nbt[DI * 64];   // nb tile transposed [d][j], j-quads swizzled by (d>>2)&7
    float aw[DI * 64];    // A [j][d] swizzled; later Wv [o][e] swizzled
    float bvec[64];       // bp, then bv
};

__device__ float g_A[DI * DI];   // A[j][d] = sum_t Wk[t][j] * Wq[t][d], row-major [j][d]
__device__ float g_bp[DI];       // bp[j]   = sum_t Wk[t][j] * bq[t]

__device__ __forceinline__ ull ffma2(ull a, ull b, ull c) {
    ull d; asm("fma.rn.f32x2 %0,%1,%2,%3;" : "=l"(d) : "l"(a), "l"(b), "l"(c)); return d;
}
__device__ __forceinline__ ull fmul2(ull a, ull b) {
    ull d; asm("mul.rn.f32x2 %0,%1,%2;" : "=l"(d) : "l"(a), "l"(b)); return d;
}
__device__ __forceinline__ ull pack2(float lo, float hi) {
    ull r; asm("mov.b64 %0,{%1,%2};" : "=l"(r) : "f"(lo), "f"(hi)); return r;
}
__device__ __forceinline__ float hadd2(ull v) {
    float lo, hi; asm("mov.b64 {%0,%1},%2;" : "=f"(lo), "=f"(hi) : "l"(v)); return lo + hi;
}

__global__ void prep_kernel(const float* __restrict__ Wq, const float* __restrict__ bq,
                            const float* __restrict__ Wk) {
    int tid = threadIdx.x;            // 256 threads
    int j = tid & 63;
    int dbase = (tid >> 6) << 4;
    for (int dd = 0; dd < 16; ++dd) {
        int d = dbase + dd;
        float s = 0.f;
        for (int t = 0; t < 64; ++t) s += Wk[t * 64 + j] * Wq[t * 64 + d];
        g_A[j * 64 + d] = s;
    }
    if (tid < 64) {
        float s = 0.f;
        for (int t = 0; t < 64; ++t) s += Wk[t * 64 + tid] * bq[t];
        g_bp[tid] = s;
    }
}

// Reduction-vectorized 8x4 micro-GEMM over a 64-long reduction dim (16 quads).
// A rows = ty8+v (stride 64, un-swizzled; loads are broadcasts within quarter-warps).
// B rows = tx4+u (stride 64, quads swizzled by sx=(row>>2)&7=tx&7; loads are bank-perms).
__device__ __forceinline__ void gemm_rv(const float* __restrict__ A, const float* __restrict__ B,
                                        int ty8, int tx4, int sx, ull acc2[8][4]) {
    #pragma unroll 4
    for (int q = 0; q < 16; ++q) {
        const int qa = q << 2;
        const int qb = (q ^ sx) << 2;
        ulonglong2 a[8], b[4];
        #pragma unroll
        for (int v = 0; v < 8; ++v) a[v] = *(const ulonglong2*)(A + (ty8 + v) * 64 + qa);
        #pragma unroll
        for (int u = 0; u < 4; ++u) b[u] = *(const ulonglong2*)(B + (tx4 + u) * 64 + qb);
        #pragma unroll
        for (int v = 0; v < 8; ++v)
            #pragma unroll
            for (int u = 0; u < 4; ++u) {
                acc2[v][u] = ffma2(a[v].x, b[u].x, acc2[v][u]);
                acc2[v][u] = ffma2(a[v].y, b[u].y, acc2[v][u]);
            }
    }
}

__global__ void __launch_bounds__(256, 1)
gat_kernel(const float* __restrict__ x, const float* __restrict__ nb,
           const float* __restrict__ Wv, const float* __restrict__ bv,
           float* __restrict__ out, int N, int M) {
    extern __shared__ float smem_raw[];
    Smem* s = reinterpret_cast<Smem*>(smem_raw);
    const int tid = threadIdx.x;
    const int tx  = tid & 15;
    const int ty  = tid >> 4;
    const int tx4 = tx << 2, ty8 = ty << 3;
    const int sx  = tx & 7;
    const int n0  = blockIdx.x * BR;

    // ---- prologue: A (swizzled) + bp + x tile (straight row-major) ----
    for (int i = tid; i < 64 * 64; i += 256) {
        int j = i >> 6, d = i & 63;
        s->aw[j * 64 + ((((d >> 2) ^ ((j >> 2) & 7)) << 2) | (d & 3))] = g_A[i];
    }
    if (tid < 64) s->bvec[tid] = g_bp[tid];
    for (int rr = ty; rr < BR; rr += 16) {
        int row = n0 + rr;
        float4 v = make_float4(0.f, 0.f, 0.f, 0.f);
        if (row < N) v = *(const float4*)&x[(size_t)row * DI + tx4];
        *(float4*)&s->ps[rr * 64 + tx4] = v;
    }
    __syncthreads();

    // ---- GEMM0: p[r][j] = bp[j] + sum_d x[r][d] * A[j][d] ----
    {
        ull acc2[8][4];
        #pragma unroll
        for (int u = 0; u < 4; ++u) {
            ull bias = pack2(s->bvec[tx4 + u], 0.f);
            #pragma unroll
            for (int v = 0; v < 8; ++v) acc2[v][u] = bias;
        }
        gemm_rv(s->ps, s->aw, ty8, tx4, sx, acc2);
        __syncthreads();   // all reads of x done before overwrite with p
        #pragma unroll
        for (int v = 0; v < 8; ++v)
            *(float4*)&s->ps[(ty8 + v) * 64 + tx4] =
                make_float4(hadd2(acc2[v][0]), hadd2(acc2[v][1]),
                            hadd2(acc2[v][2]), hadd2(acc2[v][3]));
    }

    // ---- flash loop state (aggr kept PACKED over j-parity across tiles) ----
    ull aggr[8][4];
    #pragma unroll
    for (int v = 0; v < 8; ++v)
        #pragma unroll
        for (int u = 0; u < 4; ++u) aggr[v][u] = 0ull;
    float mrow[8], lrow[8];
    #pragma unroll
    for (int v = 0; v < 8; ++v) { mrow[v] = -1e30f; lrow[v] = 0.f; }

    for (int mt = 0; mt < M; mt += BC) {
        __syncthreads();   // prior GEMM2 done with nbr/nbt/at; p visible (first iter)
        // ---- load nb tile: row-major (swizzled) + transposed (swizzled) ----
        for (int jr = ty; jr < BC; jr += 16) {
            float4 v = *(const float4*)&nb[(size_t)(mt + jr) * DI + tx4];
            *(float4*)&s->nbr[jr * 64 + ((tx ^ ((jr >> 2) & 7)) << 2)] = v;
            int col = (((jr >> 2) ^ sx) << 2) | (jr & 3);
            s->nbt[(tx4 + 0) * 64 + col] = v.x;
            s->nbt[(tx4 + 1) * 64 + col] = v.y;
            s->nbt[(tx4 + 2) * 64 + col] = v.z;
            s->nbt[(tx4 + 3) * 64 + col] = v.w;
        }
        __syncthreads();

        // ---- GEMM1: S[r][j] = sum_d p[r][d] * nb[j][d] ----
        ull acc2[8][4];
        #pragma unroll
        for (int v = 0; v < 8; ++v)
            #pragma unroll
            for (int u = 0; u < 4; ++u) acc2[v][u] = 0ull;
        gemm_rv(s->ps, s->nbr, ty8, tx4, sx, acc2);

        float S[8][4];
        #pragma unroll
        for (int v = 0; v < 8; ++v)
            #pragma unroll
            for (int u = 0; u < 4; ++u) S[v][u] = hadd2(acc2[v][u]);

        // ---- online softmax (16-lane shfl reductions) ----
        #pragma unroll
        for (int v = 0; v < 8; ++v) {
            float tm = fmaxf(fmaxf(S[v][0], S[v][1]), fmaxf(S[v][2], S[v][3]));
            tm = fmaxf(tm, __shfl_xor_sync(0xFFFFFFFFu, tm, 8, 16));
            tm = fmaxf(tm, __shfl_xor_sync(0xFFFFFFFFu, tm, 4, 16));
            tm = fmaxf(tm, __shfl_xor_sync(0xFFFFFFFFu, tm, 2, 16));
            tm = fmaxf(tm, __shfl_xor_sync(0xFFFFFFFFu, tm, 1, 16));
            float mnew = fmaxf(mrow[v], tm);
            float sc = __expf(mrow[v] - mnew);
            float rs = 0.f;
            #pragma unroll
            for (int u = 0; u < 4; ++u) { S[v][u] = __expf(S[v][u] - mnew); rs += S[v][u]; }
            rs += __shfl_xor_sync(0xFFFFFFFFu, rs, 8, 16);
            rs += __shfl_xor_sync(0xFFFFFFFFu, rs, 4, 16);
            rs += __shfl_xor_sync(0xFFFFFFFFu, rs, 2, 16);
            rs += __shfl_xor_sync(0xFFFFFFFFu, rs, 1, 16);
            lrow[v] = lrow[v] * sc + rs;
            mrow[v] = mnew;
            ull sc2 = pack2(sc, sc);
            #pragma unroll
            for (int u = 0; u < 4; ++u) aggr[v][u] = fmul2(aggr[v][u], sc2);
        }

        // ---- store attn row-major: at[r][j] (natural float4, conflict-free) ----
        #pragma unroll
        for (int v = 0; v < 8; ++v)
            *(float4*)&s->at[(ty8 + v) * 64 + tx4] =
                make_float4(S[v][0], S[v][1], S[v][2], S[v][3]);
        __syncthreads();

        // ---- GEMM2: aggr[r][e] += sum_j attn[r][j] * nbt[e][j] (into packed aggr) ----
        gemm_rv(s->at, s->nbt, ty8, tx4, sx, aggr);
    }

    // ---- epilogue: normalize agg -> ps; Wv (swizzled) -> aw; bv -> bvec ----
    float inv[8];
    #pragma unroll
    for (int v = 0; v < 8; ++v) inv[v] = 1.0f / lrow[v];
    #pragma unroll
    for (int v = 0; v < 8; ++v)
        *(float4*)&s->ps[(ty8 + v) * 64 + tx4] =
            make_float4(hadd2(aggr[v][0]) * inv[v], hadd2(aggr[v][1]) * inv[v],
                        hadd2(aggr[v][2]) * inv[v], hadd2(aggr[v][3]) * inv[v]);
    for (int i = tid; i < 64 * 64; i += 256) {
        int o = i >> 6, e = i & 63;
        s->aw[o * 64 + ((((e >> 2) ^ ((o >> 2) & 7)) << 2) | (e & 3))] = Wv[i];
    }
    if (tid < 64) s->bvec[tid] = bv[tid];
    __syncthreads();

    // ---- GEMM3: out[r][o] = bv[o] + sum_e agg[r][e] * Wv[o][e] ----
    {
        ull acc2[8][4];
        #pragma unroll
        for (int u = 0; u < 4; ++u) {
            ull bias = pack2(s->bvec[tx4 + u], 0.f);
            #pragma unroll
            for (int v = 0; v < 8; ++v) acc2[v][u] = bias;
        }
        gemm_rv(s->ps, s->aw, ty8, tx4, sx, acc2);
        #pragma unroll
        for (int v = 0; v < 8; ++v) {
            int row = n0 + ty8 + v;
            if (row < N)
                *(float4*)&out[(size_t)row * DI + tx4] =
                    make_float4(hadd2(acc2[v][0]), hadd2(acc2[v][1]),
                                hadd2(acc2[v][2]), hadd2(acc2[v][3]));
        }
    }
}

extern "C" void kernel_launch(void* const* d_in, const int* in_sizes, int n_in,
                              void* d_out, int out_size) {
    const float* x  = (const float*)d_in[0];
    const float* nb = (const float*)d_in[1];
    const float* Wq = (const float*)d_in[2];
    const float* bq = (const float*)d_in[3];
    const float* Wk = (const float*)d_in[4];
    // d_in[5] = bk: constant over m in the logits -> drops out of softmax
    const float* Wv = (const float*)d_in[6];
    const float* bv = (const float*)d_in[7];
    float* out = (float*)d_out;

    const int N = in_sizes[0] / DI;
    const int M = in_sizes[1] / DI;

    cudaFuncSetAttribute(gat_kernel, cudaFuncAttributeMaxDynamicSharedMemorySize,
                         (int)sizeof(Smem));

    prep_kernel<<<1, 256>>>(Wq, bq, Wk);
    const int grid = (N + BR - 1) / BR;
    gat_kernel<<<grid, 256, sizeof(Smem)>>>(x, nb, Wv, bv, out, N, M);
}

// round 6
// speedup vs baseline: 2.6388x; 2.6388x over previous
#include <cuda_runtime.h>
#include <cuda_fp16.h>
#include <cstdint>

#define DI 64
#define BR 128
#define STRD 72                 // halves per smem row (pad for conflict-free ldmatrix)
#define SH_B 0                  // hi image: x / nb tile (128 rows max)
#define SL_B 18432              // lo image
#define WH_B 36864              // hi: Amat, later Wv (64 rows)
#define WL_B 46080
#define BIAS_B 55296            // 64 floats
#define SM_BYTES 55552

__device__ float g_A[4096];     // A[j][d] = (Wk^T Wq)[j][d]
__device__ float g_bp[64];      // bp[j] = (Wk^T bq)[j]

static __device__ __forceinline__ uint32_t smem_u32(const void* p) {
    uint32_t a;
    asm("{.reg .u64 t; cvta.to.shared.u64 t,%1; cvt.u32.u64 %0,t;}" : "=r"(a) : "l"(p));
    return a;
}
#define LDSM4(r0,r1,r2,r3,a) asm volatile("ldmatrix.sync.aligned.m8n8.x4.shared.b16 {%0,%1,%2,%3},[%4];" \
    : "=r"(r0),"=r"(r1),"=r"(r2),"=r"(r3) : "r"(a))
#define LDSM2(r0,r1,a)  asm volatile("ldmatrix.sync.aligned.m8n8.x2.shared.b16 {%0,%1},[%2];" \
    : "=r"(r0),"=r"(r1) : "r"(a))
#define LDSM2T(r0,r1,a) asm volatile("ldmatrix.sync.aligned.m8n8.x2.trans.shared.b16 {%0,%1},[%2];" \
    : "=r"(r0),"=r"(r1) : "r"(a))
#define MMA(d,a,b) asm volatile( \
    "mma.sync.aligned.m16n8k16.row.col.f32.f16.f16.f32 {%0,%1,%2,%3},{%4,%5,%6,%7},{%8,%9},{%0,%1,%2,%3};" \
    : "+f"((d)[0]),"+f"((d)[1]),"+f"((d)[2]),"+f"((d)[3]) \
    : "r"((a)[0]),"r"((a)[1]),"r"((a)[2]),"r"((a)[3]),"r"((b)[0]),"r"((b)[1]))

static __device__ __forceinline__ uint32_t h2pack(__half a, __half b) {
    return (uint32_t)__half_as_ushort(b) << 16 | (uint32_t)__half_as_ushort(a);
}
// Dekker split of two floats into packed hi/lo half2
static __device__ __forceinline__ void split2(float x, float y, uint32_t& hi, uint32_t& lo) {
    __half hx = __float2half_rn(x), hy = __float2half_rn(y);
    __half lx = __float2half_rn(x - __half2float(hx));
    __half ly = __float2half_rn(y - __half2float(hy));
    hi = h2pack(hx, hy);
    lo = h2pack(lx, ly);
}
static __device__ __forceinline__ void split_store16(char* sm, int off_h, int off_l, const float4 v[4]) {
    uint32_t hh[8], ll[8];
    #pragma unroll
    for (int i = 0; i < 4; ++i) {
        split2(v[i].x, v[i].y, hh[2*i],   ll[2*i]);
        split2(v[i].z, v[i].w, hh[2*i+1], ll[2*i+1]);
    }
    *(uint4*)(sm + off_h)      = make_uint4(hh[0], hh[1], hh[2], hh[3]);
    *(uint4*)(sm + off_h + 16) = make_uint4(hh[4], hh[5], hh[6], hh[7]);
    *(uint4*)(sm + off_l)      = make_uint4(ll[0], ll[1], ll[2], ll[3]);
    *(uint4*)(sm + off_l + 16) = make_uint4(ll[4], ll[5], ll[6], ll[7]);
}
// D-frag (8 n-blocks x 4) -> A-frags over k (4 ksteps x 4), with optional per-row scale
static __device__ __forceinline__ void dfrag_to_afrag(const float D[8][4], float s0, float s1,
                                                      uint32_t Ah[4][4], uint32_t Al[4][4]) {
    #pragma unroll
    for (int ks = 0; ks < 4; ++ks) {
        split2(D[2*ks][0]*s0,   D[2*ks][1]*s0,   Ah[ks][0], Al[ks][0]);
        split2(D[2*ks][2]*s1,   D[2*ks][3]*s1,   Ah[ks][1], Al[ks][1]);
        split2(D[2*ks+1][0]*s0, D[2*ks+1][1]*s0, Ah[ks][2], Al[ks][2]);
        split2(D[2*ks+1][2]*s1, D[2*ks+1][3]*s1, Ah[ks][3], Al[ks][3]);
    }
}

__global__ void prep_A(const float* __restrict__ Wq, const float* __restrict__ bq,
                       const float* __restrict__ Wk) {
    int tid = threadIdx.x, j = tid & 63, dbase = (tid >> 6) << 4;
    for (int dd = 0; dd < 16; ++dd) {
        int d = dbase + dd;
        float s = 0.f;
        for (int t = 0; t < 64; ++t) s += Wk[t*64 + j] * Wq[t*64 + d];
        g_A[j*64 + d] = s;
    }
    if (tid < 64) {
        float s = 0.f;
        for (int t = 0; t < 64; ++t) s += Wk[t*64 + tid] * bq[t];
        g_bp[tid] = s;
    }
}

__global__ void __launch_bounds__(256, 1)
gat_kernel(const float* __restrict__ x, const float* __restrict__ nb,
           const float* __restrict__ Wv, const float* __restrict__ bv,
           float* __restrict__ out, int N) {
    extern __shared__ char sm[];
    const uint32_t su = smem_u32(sm);
    const int tid = threadIdx.x, lane = tid & 31, wid = tid >> 5;
    const int g = lane >> 2, tg = lane & 3;
    const int m0 = wid * 16;
    const int n0 = blockIdx.x * BR;
    float* bias = (float*)(sm + BIAS_B);

    const int prow = tid >> 2, pc = (tid & 3) * 16;   // cooperative load mapping
    // ---- prologue: x (hi/lo) -> SH/SL rows 0..127; Amat -> WH/WL; bp -> bias ----
    #pragma unroll
    for (int hh = 0; hh < 2; ++hh) {
        int rr = prow + hh * 64;
        int row = n0 + rr;
        float4 v[4];
        #pragma unroll
        for (int i = 0; i < 4; ++i)
            v[i] = (row < N) ? *(const float4*)&x[(size_t)row*DI + pc + 4*i]
                             : make_float4(0.f, 0.f, 0.f, 0.f);
        split_store16(sm, SH_B + (rr*STRD + pc)*2, SL_B + (rr*STRD + pc)*2, v);
    }
    {
        float4 a[4];
        #pragma unroll
        for (int i = 0; i < 4; ++i) a[i] = *(const float4*)&g_A[prow*64 + pc + 4*i];
        split_store16(sm, WH_B + (prow*STRD + pc)*2, WL_B + (prow*STRD + pc)*2, a);
        if (tid < 64) bias[tid] = g_bp[tid];
    }
    __syncthreads();

    // per-thread ldmatrix addressing
    const int rA = m0 + (lane & 7) + ((lane >> 3) & 1) * 8;  // A-frag row
    const int cA = ((lane >> 4) & 1) * 8;                    // A-frag col base
    const uint32_t aAh = su + SH_B + (rA*STRD + cA) * 2;     // + 32*ks bytes per kstep
    const uint32_t aAl = su + SL_B + (rA*STRD + cA) * 2;
    const int rB = lane & 7, cB = ((lane >> 3) & 1) * 8;     // B non-trans row/colbase

    // ---- GEMM0: p = x @ A^T + bp  (3-pass fp16), result stays in registers ----
    float D[8][4];
    #pragma unroll
    for (int b = 0; b < 8; ++b) {
        D[b][0] = bias[8*b + 2*tg]; D[b][1] = bias[8*b + 2*tg + 1];
        D[b][2] = D[b][0];          D[b][3] = D[b][1];
    }
    {
        uint32_t Xh[4][4], Xl[4][4];
        #pragma unroll
        for (int ks = 0; ks < 4; ++ks) {
            LDSM4(Xh[ks][0], Xh[ks][1], Xh[ks][2], Xh[ks][3], aAh + 32*ks);
            LDSM4(Xl[ks][0], Xl[ks][1], Xl[ks][2], Xl[ks][3], aAl + 32*ks);
        }
        #pragma unroll
        for (int ks = 0; ks < 4; ++ks)
            #pragma unroll
            for (int b = 0; b < 8; ++b) {
                uint32_t bh[2], bl[2];
                uint32_t ba = ((8*b + rB)*STRD + 16*ks + cB) * 2;
                LDSM2(bh[0], bh[1], su + WH_B + ba);
                LDSM2(bl[0], bl[1], su + WL_B + ba);
                MMA(D[b], Xh[ks], bh);
                MMA(D[b], Xl[ks], bh);
                MMA(D[b], Xh[ks], bl);
            }
    }
    uint32_t Ph[4][4], Pl[4][4];
    dfrag_to_afrag(D, 1.f, 1.f, Ph, Pl);

    // ---- flash loop ----
    float ag[8][4];
    #pragma unroll
    for (int b = 0; b < 8; ++b)
        #pragma unroll
        for (int u = 0; u < 4; ++u) ag[b][u] = 0.f;
    float mr0 = -1e30f, mr1 = -1e30f, lr0 = 0.f, lr1 = 0.f;

    for (int t = 0; t < 16; ++t) {
        // prefetch nb tile chunk (L2-resident) into regs
        float4 v[4];
        #pragma unroll
        for (int i = 0; i < 4; ++i)
            v[i] = *(const float4*)&nb[(size_t)(t*64 + prow)*DI + pc + 4*i];
        __syncthreads();   // prior tile's reads of SH/SL done
        split_store16(sm, SH_B + (prow*STRD + pc)*2, SL_B + (prow*STRD + pc)*2, v);
        __syncthreads();

        // GEMM1: S = p @ nb^T (B rows = n = j, non-trans)
        float S[8][4];
        #pragma unroll
        for (int b = 0; b < 8; ++b)
            #pragma unroll
            for (int u = 0; u < 4; ++u) S[b][u] = 0.f;
        #pragma unroll
        for (int ks = 0; ks < 4; ++ks)
            #pragma unroll
            for (int b = 0; b < 8; ++b) {
                uint32_t bh[2], bl[2];
                uint32_t ba = ((8*b + rB)*STRD + 16*ks + cB) * 2;
                LDSM2(bh[0], bh[1], su + SH_B + ba);
                LDSM2(bl[0], bl[1], su + SL_B + ba);
                MMA(S[b], Ph[ks], bh);
                MMA(S[b], Pl[ks], bh);
                MMA(S[b], Ph[ks], bl);
            }

        // online softmax (rows g and g+8; reduce over 4 lanes)
        float mx0 = -1e30f, mx1 = -1e30f;
        #pragma unroll
        for (int b = 0; b < 8; ++b) {
            mx0 = fmaxf(mx0, fmaxf(S[b][0], S[b][1]));
            mx1 = fmaxf(mx1, fmaxf(S[b][2], S[b][3]));
        }
        mx0 = fmaxf(mx0, __shfl_xor_sync(0xFFFFFFFFu, mx0, 1));
        mx0 = fmaxf(mx0, __shfl_xor_sync(0xFFFFFFFFu, mx0, 2));
        mx1 = fmaxf(mx1, __shfl_xor_sync(0xFFFFFFFFu, mx1, 1));
        mx1 = fmaxf(mx1, __shfl_xor_sync(0xFFFFFFFFu, mx1, 2));
        float mn0 = fmaxf(mr0, mx0), mn1 = fmaxf(mr1, mx1);
        float sc0 = __expf(mr0 - mn0), sc1 = __expf(mr1 - mn1);
        mr0 = mn0; mr1 = mn1;
        float s0 = 0.f, s1 = 0.f;
        #pragma unroll
        for (int b = 0; b < 8; ++b) {
            S[b][0] = __expf(S[b][0] - mn0); s0 += S[b][0];
            S[b][1] = __expf(S[b][1] - mn0); s0 += S[b][1];
            S[b][2] = __expf(S[b][2] - mn1); s1 += S[b][2];
            S[b][3] = __expf(S[b][3] - mn1); s1 += S[b][3];
        }
        s0 += __shfl_xor_sync(0xFFFFFFFFu, s0, 1);
        s0 += __shfl_xor_sync(0xFFFFFFFFu, s0, 2);
        s1 += __shfl_xor_sync(0xFFFFFFFFu, s1, 1);
        s1 += __shfl_xor_sync(0xFFFFFFFFu, s1, 2);
        lr0 = lr0 * sc0 + s0;
        lr1 = lr1 * sc1 + s1;

        // attn -> A-frags (registers), rescale aggr
        uint32_t Th[4][4], Tl[4][4];
        dfrag_to_afrag(S, 1.f, 1.f, Th, Tl);
        #pragma unroll
        for (int b = 0; b < 8; ++b) {
            ag[b][0] *= sc0; ag[b][1] *= sc0;
            ag[b][2] *= sc1; ag[b][3] *= sc1;
        }

        // GEMM2: ag += attn @ nb (B rows = k = j, trans)
        #pragma unroll
        for (int ks = 0; ks < 4; ++ks)
            #pragma unroll
            for (int b = 0; b < 8; ++b) {
                uint32_t bh[2], bl[2];
                uint32_t ba = ((16*ks + cB + rB)*STRD + 8*b) * 2;
                LDSM2T(bh[0], bh[1], su + SH_B + ba);
                LDSM2T(bl[0], bl[1], su + SL_B + ba);
                MMA(ag[b], Th[ks], bh);
                MMA(ag[b], Tl[ks], bh);
                MMA(ag[b], Th[ks], bl);
            }
    }

    // ---- epilogue: normalize -> A-frags; Wv -> WH/WL; GEMM3; store ----
    float inv0 = 1.0f / lr0, inv1 = 1.0f / lr1;
    uint32_t Gh[4][4], Gl[4][4];
    dfrag_to_afrag(ag, inv0, inv1, Gh, Gl);
    {
        float4 w4[4];
        #pragma unroll
        for (int i = 0; i < 4; ++i) w4[i] = *(const float4*)&Wv[prow*64 + pc + 4*i];
        split_store16(sm, WH_B + (prow*STRD + pc)*2, WL_B + (prow*STRD + pc)*2, w4);
        if (tid < 64) bias[tid] = bv[tid];
    }
    __syncthreads();
    float O[8][4];
    #pragma unroll
    for (int b = 0; b < 8; ++b) {
        O[b][0] = bias[8*b + 2*tg]; O[b][1] = bias[8*b + 2*tg + 1];
        O[b][2] = O[b][0];          O[b][3] = O[b][1];
    }
    #pragma unroll
    for (int ks = 0; ks < 4; ++ks)
        #pragma unroll
        for (int b = 0; b < 8; ++b) {
            uint32_t bh[2], bl[2];
            uint32_t ba = ((8*b + rB)*STRD + 16*ks + cB) * 2;
            LDSM2(bh[0], bh[1], su + WH_B + ba);
            LDSM2(bl[0], bl[1], su + WL_B + ba);
            MMA(O[b], Gh[ks], bh);
            MMA(O[b], Gl[ks], bh);
            MMA(O[b], Gh[ks], bl);
        }
    #pragma unroll
    for (int b = 0; b < 8; ++b) {
        int col = 8*b + 2*tg;
        int row0 = n0 + m0 + g;
        if (row0 < N) *(float2*)&out[(size_t)row0*DI + col] = make_float2(O[b][0], O[b][1]);
        int row1 = row0 + 8;
        if (row1 < N) *(float2*)&out[(size_t)row1*DI + col] = make_float2(O[b][2], O[b][3]);
    }
}

extern "C" void kernel_launch(void* const* d_in, const int* in_sizes, int n_in,
                              void* d_out, int out_size) {
    const float* x  = (const float*)d_in[0];
    const float* nb = (const float*)d_in[1];
    const float* Wq = (const float*)d_in[2];
    const float* bq = (const float*)d_in[3];
    const float* Wk = (const float*)d_in[4];
    // d_in[5] = bk drops out of softmax
    const float* Wv = (const float*)d_in[6];
    const float* bv = (const float*)d_in[7];
    float* out = (float*)d_out;
    const int N = in_sizes[0] / DI;
    cudaFuncSetAttribute(gat_kernel, cudaFuncAttributeMaxDynamicSharedMemorySize, SM_BYTES);
    prep_A<<<1, 256>>>(Wq, bq, Wk);
    gat_kernel<<<(N + BR - 1) / BR, 256, SM_BYTES>>>(x, nb, Wv, bv, out, N);
}

// round 7
// speedup vs baseline: 3.2346x; 1.2258x over previous
#include <cuda_runtime.h>
#include <cuda_fp16.h>
#include <cstdint>

#define DI 64
#define BR 128
#define STRD 72                 // halves per smem row (144B; conflict-free ldmatrix)
#define STG_BYTES 18432         // one stage: H image (9216B) + L image (9216B)
#define WH_B 36864              // Amat / Wv hi (64 rows x 144B)
#define WL_B 46080
#define BIAS_B 55296
#define SM_BYTES 55552

__device__ float g_A[4096];             // A[j][d] = (Wk^T Wq)[j][d]
__device__ float g_bp[64];              // bp[j] = (Wk^T bq)[j]
__device__ __half g_nb[16 * 9216];      // per tile: [hi 64x72 | lo 64x72] halves

static __device__ __forceinline__ uint32_t smem_u32(const void* p) {
    uint32_t a;
    asm("{.reg .u64 t; cvta.to.shared.u64 t,%1; cvt.u32.u64 %0,t;}" : "=r"(a) : "l"(p));
    return a;
}
#define LDSM4(r0,r1,r2,r3,a) asm volatile("ldmatrix.sync.aligned.m8n8.x4.shared.b16 {%0,%1,%2,%3},[%4];" \
    : "=r"(r0),"=r"(r1),"=r"(r2),"=r"(r3) : "r"(a))
#define LDSM4T(r0,r1,r2,r3,a) asm volatile("ldmatrix.sync.aligned.m8n8.x4.trans.shared.b16 {%0,%1,%2,%3},[%4];" \
    : "=r"(r0),"=r"(r1),"=r"(r2),"=r"(r3) : "r"(a))
#define MMA(d,a,b) asm volatile( \
    "mma.sync.aligned.m16n8k16.row.col.f32.f16.f16.f32 {%0,%1,%2,%3},{%4,%5,%6,%7},{%8,%9},{%0,%1,%2,%3};" \
    : "+f"((d)[0]),"+f"((d)[1]),"+f"((d)[2]),"+f"((d)[3]) \
    : "r"((a)[0]),"r"((a)[1]),"r"((a)[2]),"r"((a)[3]),"r"((b)[0]),"r"((b)[1]))
#define CPA16(dst, src)  asm volatile("cp.async.ca.shared.global [%0],[%1],16;" :: "r"(dst), "l"(src))
#define CPA_COMMIT()     asm volatile("cp.async.commit_group;" ::: "memory")
#define CPA_WAIT0()      asm volatile("cp.async.wait_group 0;" ::: "memory")

static __device__ __forceinline__ uint32_t h2pack(__half a, __half b) {
    return (uint32_t)__half_as_ushort(b) << 16 | (uint32_t)__half_as_ushort(a);
}
static __device__ __forceinline__ void split2(float x, float y, uint32_t& hi, uint32_t& lo) {
    __half hx = __float2half_rn(x), hy = __float2half_rn(y);
    __half lx = __float2half_rn(x - __half2float(hx));
    __half ly = __float2half_rn(y - __half2float(hy));
    hi = h2pack(hx, hy);
    lo = h2pack(lx, ly);
}
static __device__ __forceinline__ void split_store16(char* sm, int off_h, int off_l, const float4 v[4]) {
    uint32_t hh[8], ll[8];
    #pragma unroll
    for (int i = 0; i < 4; ++i) {
        split2(v[i].x, v[i].y, hh[2*i],   ll[2*i]);
        split2(v[i].z, v[i].w, hh[2*i+1], ll[2*i+1]);
    }
    *(uint4*)(sm + off_h)      = make_uint4(hh[0], hh[1], hh[2], hh[3]);
    *(uint4*)(sm + off_h + 16) = make_uint4(hh[4], hh[5], hh[6], hh[7]);
    *(uint4*)(sm + off_l)      = make_uint4(ll[0], ll[1], ll[2], ll[3]);
    *(uint4*)(sm + off_l + 16) = make_uint4(ll[4], ll[5], ll[6], ll[7]);
}
// D-frag (8 n-blocks x 4) -> A-frags over k (4 ksteps x 4) with per-row scales
static __device__ __forceinline__ void dfrag_to_afrag(const float D[8][4], float s0, float s1,
                                                      uint32_t Ah[4][4], uint32_t Al[4][4]) {
    #pragma unroll
    for (int ks = 0; ks < 4; ++ks) {
        split2(D[2*ks][0]*s0,   D[2*ks][1]*s0,   Ah[ks][0], Al[ks][0]);
        split2(D[2*ks][2]*s1,   D[2*ks][3]*s1,   Ah[ks][1], Al[ks][1]);
        split2(D[2*ks+1][0]*s0, D[2*ks+1][1]*s0, Ah[ks][2], Al[ks][2]);
        split2(D[2*ks+1][2]*s1, D[2*ks+1][3]*s1, Ah[ks][3], Al[ks][3]);
    }
}

__global__ void prep_A(const float* __restrict__ Wq, const float* __restrict__ bq,
                       const float* __restrict__ Wk) {
    int tid = threadIdx.x, j = tid & 63, dbase = (tid >> 6) << 4;
    for (int dd = 0; dd < 16; ++dd) {
        int d = dbase + dd;
        float s = 0.f;
        for (int t = 0; t < 64; ++t) s += Wk[t*64 + j] * Wq[t*64 + d];
        g_A[j*64 + d] = s;
    }
    if (tid < 64) {
        float s = 0.f;
        for (int t = 0; t < 64; ++t) s += Wk[t*64 + tid] * bq[t];
        g_bp[tid] = s;
    }
}
__global__ void prep_nb(const float* __restrict__ nb) {
    int idx = blockIdx.x * 256 + threadIdx.x;   // 65536
    int row = idx >> 6, d = idx & 63;
    int t = row >> 6, j = row & 63;
    float v = nb[idx];
    __half h = __float2half_rn(v);
    __half l = __float2half_rn(v - __half2float(h));
    g_nb[t*9216 + j*STRD + d] = h;
    g_nb[t*9216 + 4608 + j*STRD + d] = l;
}

__global__ void __launch_bounds__(256, 2)
gat_kernel(const float* __restrict__ x, const float* __restrict__ Wv,
           const float* __restrict__ bv, float* __restrict__ out, int N) {
    extern __shared__ char sm[];
    const uint32_t su = smem_u32(sm);
    const int tid = threadIdx.x, lane = tid & 31, wid = tid >> 5;
    const int g = lane >> 2, tg = lane & 3;
    const int m0 = wid * 16;
    const int n0 = blockIdx.x * BR;
    float* bias = (float*)(sm + BIAS_B);

    // lane-derived ldmatrix address components
    const int rN = ((lane >> 4) & 1) * 8 + (lane & 7);  // non-trans: row-within-pair
    const int cN = ((lane >> 3) & 1) * 8;               // non-trans: col offset
    const int rT = ((lane >> 3) & 1) * 8 + (lane & 7);  // trans: row offset
    const int cT = ((lane >> 4) & 1) * 8;               // trans: col-within-pair

    // ---- start tile-0 copy immediately ----
    {
        const char* src = (const char*)g_nb;
        for (int i = tid; i < 1152; i += 256) CPA16(su + i*16, src + i*16);
        CPA_COMMIT();
    }
    // ---- prologue: Amat (hi/lo) -> WH/WL, bp -> bias; x frags direct from global ----
    const int prow = tid >> 2, pc = (tid & 3) * 16;
    {
        float4 a[4];
        #pragma unroll
        for (int i = 0; i < 4; ++i) a[i] = *(const float4*)&g_A[prow*64 + pc + 4*i];
        split_store16(sm, WH_B + (prow*STRD + pc)*2, WL_B + (prow*STRD + pc)*2, a);
        if (tid < 64) bias[tid] = g_bp[tid];
    }
    uint32_t Xh[4][4], Xl[4][4];
    {
        int r0 = n0 + m0 + g, r1 = r0 + 8;
        #pragma unroll
        for (int q = 0; q < 8; ++q) {
            int c = 2*tg + 8*q;
            float2 v0 = make_float2(0.f, 0.f), v1 = make_float2(0.f, 0.f);
            if (r0 < N) v0 = *(const float2*)&x[(size_t)r0*DI + c];
            if (r1 < N) v1 = *(const float2*)&x[(size_t)r1*DI + c];
            int ks = q >> 1;
            if ((q & 1) == 0) {
                split2(v0.x, v0.y, Xh[ks][0], Xl[ks][0]);
                split2(v1.x, v1.y, Xh[ks][1], Xl[ks][1]);
            } else {
                split2(v0.x, v0.y, Xh[ks][2], Xl[ks][2]);
                split2(v1.x, v1.y, Xh[ks][3], Xl[ks][3]);
            }
        }
    }
    __syncthreads();

    // ---- GEMM0: p = x @ A^T + bp ----
    float D[8][4];
    #pragma unroll
    for (int b = 0; b < 8; ++b) {
        D[b][0] = bias[8*b + 2*tg]; D[b][1] = bias[8*b + 2*tg + 1];
        D[b][2] = D[b][0];          D[b][3] = D[b][1];
    }
    #pragma unroll
    for (int ks = 0; ks < 4; ++ks)
        #pragma unroll
        for (int P = 0; P < 4; ++P) {
            uint32_t off = ((16*P + rN)*STRD + 16*ks + cN) * 2;
            uint32_t bh[4], bl[4];
            LDSM4(bh[0], bh[1], bh[2], bh[3], su + WH_B + off);
            LDSM4(bl[0], bl[1], bl[2], bl[3], su + WL_B + off);
            MMA(D[2*P],   Xh[ks], bh);     MMA(D[2*P],   Xl[ks], bh);     MMA(D[2*P],   Xh[ks], bl);
            MMA(D[2*P+1], Xh[ks], bh+2);   MMA(D[2*P+1], Xl[ks], bh+2);   MMA(D[2*P+1], Xh[ks], bl+2);
        }
    uint32_t Ph[4][4], Pl[4][4];
    dfrag_to_afrag(D, 1.f, 1.f, Ph, Pl);

    // ---- flash loop (double-buffered nb stages) ----
    float ag[8][4];
    #pragma unroll
    for (int b = 0; b < 8; ++b)
        #pragma unroll
        for (int u = 0; u < 4; ++u) ag[b][u] = 0.f;
    float mr0 = -1e30f, mr1 = -1e30f, lr0 = 0.f, lr1 = 0.f;

    for (int t = 0; t < 16; ++t) {
        CPA_WAIT0();          // tile t landed
        __syncthreads();      // visible to all; all warps past tile t-1 compute
        if (t + 1 < 16) {     // prefetch t+1 into the other stage
            uint32_t dst = su + ((t + 1) & 1) * STG_BYTES;
            const char* src = (const char*)g_nb + (t + 1) * STG_BYTES;
            for (int i = tid; i < 1152; i += 256) CPA16(dst + i*16, src + i*16);
            CPA_COMMIT();
        }
        const uint32_t sH = su + (t & 1) * STG_BYTES;
        const uint32_t sL = sH + 9216;

        // GEMM1: S = p @ nb^T
        float S[8][4];
        #pragma unroll
        for (int b = 0; b < 8; ++b)
            #pragma unroll
            for (int u = 0; u < 4; ++u) S[b][u] = 0.f;
        #pragma unroll
        for (int ks = 0; ks < 4; ++ks)
            #pragma unroll
            for (int P = 0; P < 4; ++P) {
                uint32_t off = ((16*P + rN)*STRD + 16*ks + cN) * 2;
                uint32_t bh[4], bl[4];
                LDSM4(bh[0], bh[1], bh[2], bh[3], sH + off);
                LDSM4(bl[0], bl[1], bl[2], bl[3], sL + off);
                MMA(S[2*P],   Ph[ks], bh);   MMA(S[2*P],   Pl[ks], bh);   MMA(S[2*P],   Ph[ks], bl);
                MMA(S[2*P+1], Ph[ks], bh+2); MMA(S[2*P+1], Pl[ks], bh+2); MMA(S[2*P+1], Ph[ks], bl+2);
            }

        // online softmax (rows g, g+8; reduce over 4 lanes)
        float mx0 = -1e30f, mx1 = -1e30f;
        #pragma unroll
        for (int b = 0; b < 8; ++b) {
            mx0 = fmaxf(mx0, fmaxf(S[b][0], S[b][1]));
            mx1 = fmaxf(mx1, fmaxf(S[b][2], S[b][3]));
        }
        mx0 = fmaxf(mx0, __shfl_xor_sync(0xFFFFFFFFu, mx0, 1));
        mx0 = fmaxf(mx0, __shfl_xor_sync(0xFFFFFFFFu, mx0, 2));
        mx1 = fmaxf(mx1, __shfl_xor_sync(0xFFFFFFFFu, mx1, 1));
        mx1 = fmaxf(mx1, __shfl_xor_sync(0xFFFFFFFFu, mx1, 2));
        float mn0 = fmaxf(mr0, mx0), mn1 = fmaxf(mr1, mx1);
        float sc0 = __expf(mr0 - mn0), sc1 = __expf(mr1 - mn1);
        mr0 = mn0; mr1 = mn1;
        float s0 = 0.f, s1 = 0.f;
        #pragma unroll
        for (int b = 0; b < 8; ++b) {
            S[b][0] = __expf(S[b][0] - mn0); s0 += S[b][0];
            S[b][1] = __expf(S[b][1] - mn0); s0 += S[b][1];
            S[b][2] = __expf(S[b][2] - mn1); s1 += S[b][2];
            S[b][3] = __expf(S[b][3] - mn1); s1 += S[b][3];
        }
        s0 += __shfl_xor_sync(0xFFFFFFFFu, s0, 1);
        s0 += __shfl_xor_sync(0xFFFFFFFFu, s0, 2);
        s1 += __shfl_xor_sync(0xFFFFFFFFu, s1, 1);
        s1 += __shfl_xor_sync(0xFFFFFFFFu, s1, 2);
        lr0 = lr0 * sc0 + s0;
        lr1 = lr1 * sc1 + s1;

        uint32_t Th[4][4], Tl[4][4];
        dfrag_to_afrag(S, 1.f, 1.f, Th, Tl);
        #pragma unroll
        for (int b = 0; b < 8; ++b) {
            ag[b][0] *= sc0; ag[b][1] *= sc0;
            ag[b][2] *= sc1; ag[b][3] *= sc1;
        }

        // GEMM2: ag += attn @ nb (trans B)
        #pragma unroll
        for (int ks = 0; ks < 4; ++ks)
            #pragma unroll
            for (int P = 0; P < 4; ++P) {
                uint32_t off = ((16*ks + rT)*STRD + 16*P + cT) * 2;
                uint32_t bh[4], bl[4];
                LDSM4T(bh[0], bh[1], bh[2], bh[3], sH + off);
                LDSM4T(bl[0], bl[1], bl[2], bl[3], sL + off);
                MMA(ag[2*P],   Th[ks], bh);   MMA(ag[2*P],   Tl[ks], bh);   MMA(ag[2*P],   Th[ks], bl);
                MMA(ag[2*P+1], Th[ks], bh+2); MMA(ag[2*P+1], Tl[ks], bh+2); MMA(ag[2*P+1], Th[ks], bl+2);
            }
    }

    // ---- epilogue: normalize -> A-frags; Wv -> WH/WL; GEMM3; store ----
    float inv0 = 1.0f / lr0, inv1 = 1.0f / lr1;
    uint32_t Gh[4][4], Gl[4][4];
    dfrag_to_afrag(ag, inv0, inv1, Gh, Gl);
    {
        float4 w4[4];
        #pragma unroll
        for (int i = 0; i < 4; ++i) w4[i] = *(const float4*)&Wv[prow*64 + pc + 4*i];
        split_store16(sm, WH_B + (prow*STRD + pc)*2, WL_B + (prow*STRD + pc)*2, w4);
        if (tid < 64) bias[tid] = bv[tid];
    }
    __syncthreads();
    float O[8][4];
    #pragma unroll
    for (int b = 0; b < 8; ++b) {
        O[b][0] = bias[8*b + 2*tg]; O[b][1] = bias[8*b + 2*tg + 1];
        O[b][2] = O[b][0];          O[b][3] = O[b][1];
    }
    #pragma unroll
    for (int ks = 0; ks < 4; ++ks)
        #pragma unroll
        for (int P = 0; P < 4; ++P) {
            uint32_t off = ((16*P + rN)*STRD + 16*ks + cN) * 2;
            uint32_t bh[4], bl[4];
            LDSM4(bh[0], bh[1], bh[2], bh[3], su + WH_B + off);
            LDSM4(bl[0], bl[1], bl[2], bl[3], su + WL_B + off);
            MMA(O[2*P],   Gh[ks], bh);   MMA(O[2*P],   Gl[ks], bh);   MMA(O[2*P],   Gh[ks], bl);
            MMA(O[2*P+1], Gh[ks], bh+2); MMA(O[2*P+1], Gl[ks], bh+2); MMA(O[2*P+1], Gh[ks], bl+2);
        }
    #pragma unroll
    for (int b = 0; b < 8; ++b) {
        int col = 8*b + 2*tg;
        int row0 = n0 + m0 + g;
        if (row0 < N) *(float2*)&out[(size_t)row0*DI + col] = make_float2(O[b][0], O[b][1]);
        int row1 = row0 + 8;
        if (row1 < N) *(float2*)&out[(size_t)row1*DI + col] = make_float2(O[b][2], O[b][3]);
    }
}

extern "C" void kernel_launch(void* const* d_in, const int* in_sizes, int n_in,
                              void* d_out, int out_size) {
    const float* x  = (const float*)d_in[0];
    const float* nb = (const float*)d_in[1];
    const float* Wq = (const float*)d_in[2];
    const float* bq = (const float*)d_in[3];
    const float* Wk = (const float*)d_in[4];
    // d_in[5] = bk drops out of softmax
    const float* Wv = (const float*)d_in[6];
    const float* bv = (const float*)d_in[7];
    float* out = (float*)d_out;
    const int N = in_sizes[0] / DI;
    cudaFuncSetAttribute(gat_kernel, cudaFuncAttributeMaxDynamicSharedMemorySize, SM_BYTES);
    prep_A<<<1, 256>>>(Wq, bq, Wk);
    prep_nb<<<256, 256>>>(nb);
    gat_kernel<<<(N + BR - 1) / BR, 256, SM_BYTES>>>(x, Wv, bv, out, N);
}

// round 8
// speedup vs baseline: 3.4022x; 1.0518x over previous
#include <cuda_runtime.h>
#include <cuda_fp16.h>
#include <cstdint>

#define DI 64
#define BR 128
#define STRD 72                 // halves per smem row (144B; conflict-free ldmatrix)
#define STG_BYTES 18432         // one stage: H image (9216B) + L image (9216B)
#define WH_B 36864              // weight image region (A, then Wv): H + L contiguous
#define BIAS_B 55296
#define SM_BYTES 55552

__device__ float g_A[4096];                       // A[j][d] = (Wk^T Wq)[j][d]
__device__ float g_bp[64];                        // bp[j] = (Wk^T bq)[j]
__device__ __align__(16) __half g_nb[16 * 9216];  // per tile: [hi 64x72 | lo 64x72]
__device__ __align__(16) __half g_wA[9216];       // A image  [hi 64x72 | lo 64x72]
__device__ __align__(16) __half g_wV[9216];       // Wv image

static __device__ __forceinline__ uint32_t smem_u32(const void* p) {
    uint32_t a;
    asm("{.reg .u64 t; cvta.to.shared.u64 t,%1; cvt.u32.u64 %0,t;}" : "=r"(a) : "l"(p));
    return a;
}
#define LDSM4(r0,r1,r2,r3,a) asm volatile("ldmatrix.sync.aligned.m8n8.x4.shared.b16 {%0,%1,%2,%3},[%4];" \
    : "=r"(r0),"=r"(r1),"=r"(r2),"=r"(r3) : "r"(a))
#define LDSM4T(r0,r1,r2,r3,a) asm volatile("ldmatrix.sync.aligned.m8n8.x4.trans.shared.b16 {%0,%1,%2,%3},[%4];" \
    : "=r"(r0),"=r"(r1),"=r"(r2),"=r"(r3) : "r"(a))
#define MMA(d,a,b) asm volatile( \
    "mma.sync.aligned.m16n8k16.row.col.f32.f16.f16.f32 {%0,%1,%2,%3},{%4,%5,%6,%7},{%8,%9},{%0,%1,%2,%3};" \
    : "+f"((d)[0]),"+f"((d)[1]),"+f"((d)[2]),"+f"((d)[3]) \
    : "r"((a)[0]),"r"((a)[1]),"r"((a)[2]),"r"((a)[3]),"r"((b)[0]),"r"((b)[1]))
#define CPA16(dst, src)  asm volatile("cp.async.ca.shared.global [%0],[%1],16;" :: "r"(dst), "l"(src))
#define CPA_COMMIT()     asm volatile("cp.async.commit_group;" ::: "memory")
#define CPA_WAIT0()      asm volatile("cp.async.wait_group 0;" ::: "memory")

static __device__ __forceinline__ uint32_t h2pack(__half a, __half b) {
    return (uint32_t)__half_as_ushort(b) << 16 | (uint32_t)__half_as_ushort(a);
}
static __device__ __forceinline__ void split2(float x, float y, uint32_t& hi, uint32_t& lo) {
    __half hx = __float2half_rn(x), hy = __float2half_rn(y);
    __half lx = __float2half_rn(x - __half2float(hx));
    __half ly = __float2half_rn(y - __half2float(hy));
    hi = h2pack(hx, hy);
    lo = h2pack(lx, ly);
}
// D-frag (8 n-blocks x 4) -> A-frags over k (4 ksteps x 4) with per-row scales
static __device__ __forceinline__ void dfrag_to_afrag(const float D[8][4], float s0, float s1,
                                                      uint32_t Ah[4][4], uint32_t Al[4][4]) {
    #pragma unroll
    for (int ks = 0; ks < 4; ++ks) {
        split2(D[2*ks][0]*s0,   D[2*ks][1]*s0,   Ah[ks][0], Al[ks][0]);
        split2(D[2*ks][2]*s1,   D[2*ks][3]*s1,   Ah[ks][1], Al[ks][1]);
        split2(D[2*ks+1][0]*s0, D[2*ks+1][1]*s0, Ah[ks][2], Al[ks][2]);
        split2(D[2*ks+1][2]*s1, D[2*ks+1][3]*s1, Ah[ks][3], Al[ks][3]);
    }
}

// grid 16 x 256: one output element per thread
__global__ void prep_A(const float* __restrict__ Wq, const float* __restrict__ bq,
                       const float* __restrict__ Wk) {
    int idx = blockIdx.x * 256 + threadIdx.x;
    int j = idx >> 6, d = idx & 63;
    float s = 0.f;
    #pragma unroll 8
    for (int t = 0; t < 64; ++t) s += Wk[t*64 + j] * Wq[t*64 + d];
    g_A[idx] = s;
    if (blockIdx.x == 0 && threadIdx.x < 64) {
        int jj = threadIdx.x;
        float b = 0.f;
        #pragma unroll 8
        for (int t = 0; t < 64; ++t) b += Wk[t*64 + jj] * bq[t];
        g_bp[jj] = b;
    }
}
// grid 288 x 256: blocks 0-255 -> nb images; 256-271 -> A image; 272-287 -> Wv image
__global__ void prep_img(const float* __restrict__ nb, const float* __restrict__ Wv) {
    int b = blockIdx.x;
    if (b < 256) {
        int idx = b * 256 + threadIdx.x;          // 65536
        int row = idx >> 6, d = idx & 63;
        int t = row >> 6, j = row & 63;
        float v = nb[idx];
        __half h = __float2half_rn(v);
        __half l = __float2half_rn(v - __half2float(h));
        g_nb[t*9216 + j*STRD + d] = h;
        g_nb[t*9216 + 4608 + j*STRD + d] = l;
    } else if (b < 272) {
        int idx = (b - 256) * 256 + threadIdx.x;  // 4096
        int j = idx >> 6, d = idx & 63;
        float v = g_A[idx];
        __half h = __float2half_rn(v);
        __half l = __float2half_rn(v - __half2float(h));
        g_wA[j*STRD + d] = h;
        g_wA[4608 + j*STRD + d] = l;
    } else {
        int idx = (b - 272) * 256 + threadIdx.x;  // 4096
        int o = idx >> 6, e = idx & 63;
        float v = Wv[idx];
        __half h = __float2half_rn(v);
        __half l = __float2half_rn(v - __half2float(h));
        g_wV[o*STRD + e] = h;
        g_wV[4608 + o*STRD + e] = l;
    }
}

__global__ void __launch_bounds__(256, 2)
gat_kernel(const float* __restrict__ x, const float* __restrict__ bv,
           float* __restrict__ out, int N) {
    extern __shared__ char sm[];
    const uint32_t su = smem_u32(sm);
    const int tid = threadIdx.x, lane = tid & 31, wid = tid >> 5;
    const int g = lane >> 2, tg = lane & 3;
    const int m0 = wid * 16;
    const int n0 = blockIdx.x * BR;
    float* bias = (float*)(sm + BIAS_B);

    // lane-derived ldmatrix address components
    const int rN = ((lane >> 4) & 1) * 8 + (lane & 7);
    const int cN = ((lane >> 3) & 1) * 8;
    const int rT = ((lane >> 3) & 1) * 8 + (lane & 7);
    const int cT = ((lane >> 4) & 1) * 8;

    // ---- start tile-0 + A-image copies immediately ----
    {
        const char* s0 = (const char*)g_nb;
        const char* sa = (const char*)g_wA;
        for (int i = tid; i < 1152; i += 256) {
            CPA16(su + i*16, s0 + i*16);
            CPA16(su + WH_B + i*16, sa + i*16);
        }
        CPA_COMMIT();
    }
    if (tid < 64) bias[tid] = g_bp[tid];

    // ---- x fragments straight from global (hidden behind copies) ----
    uint32_t Xh[4][4], Xl[4][4];
    {
        int r0 = n0 + m0 + g, r1 = r0 + 8;
        #pragma unroll
        for (int q = 0; q < 8; ++q) {
            int c = 2*tg + 8*q;
            float2 v0 = make_float2(0.f, 0.f), v1 = make_float2(0.f, 0.f);
            if (r0 < N) v0 = *(const float2*)&x[(size_t)r0*DI + c];
            if (r1 < N) v1 = *(const float2*)&x[(size_t)r1*DI + c];
            int ks = q >> 1;
            if ((q & 1) == 0) {
                split2(v0.x, v0.y, Xh[ks][0], Xl[ks][0]);
                split2(v1.x, v1.y, Xh[ks][1], Xl[ks][1]);
            } else {
                split2(v0.x, v0.y, Xh[ks][2], Xl[ks][2]);
                split2(v1.x, v1.y, Xh[ks][3], Xl[ks][3]);
            }
        }
    }
    CPA_WAIT0();
    __syncthreads();

    // ---- GEMM0: p = x @ A^T + bp ----
    float D[8][4];
    #pragma unroll
    for (int b = 0; b < 8; ++b) {
        D[b][0] = bias[8*b + 2*tg]; D[b][1] = bias[8*b + 2*tg + 1];
        D[b][2] = D[b][0];          D[b][3] = D[b][1];
    }
    #pragma unroll
    for (int ks = 0; ks < 4; ++ks)
        #pragma unroll
        for (int P = 0; P < 4; ++P) {
            uint32_t off = ((16*P + rN)*STRD + 16*ks + cN) * 2;
            uint32_t bh[4], bl[4];
            LDSM4(bh[0], bh[1], bh[2], bh[3], su + WH_B + off);
            LDSM4(bl[0], bl[1], bl[2], bl[3], su + WH_B + 9216 + off);
            MMA(D[2*P],   Xh[ks], bh);     MMA(D[2*P],   Xl[ks], bh);     MMA(D[2*P],   Xh[ks], bl);
            MMA(D[2*P+1], Xh[ks], bh+2);   MMA(D[2*P+1], Xl[ks], bh+2);   MMA(D[2*P+1], Xh[ks], bl+2);
        }
    uint32_t Ph[4][4], Pl[4][4];
    dfrag_to_afrag(D, 1.f, 1.f, Ph, Pl);

    // ---- flash loop (double-buffered nb stages) ----
    float ag[8][4];
    #pragma unroll
    for (int b = 0; b < 8; ++b)
        #pragma unroll
        for (int u = 0; u < 4; ++u) ag[b][u] = 0.f;
    float mr0 = -1e30f, mr1 = -1e30f, lr0 = 0.f, lr1 = 0.f;

    for (int t = 0; t < 16; ++t) {
        CPA_WAIT0();          // tile t landed
        __syncthreads();      // all warps past tile t-1 compute; GEMM0 WH reads done (t==0)
        if (t + 1 < 16) {     // prefetch t+1 into the other stage
            uint32_t dst = su + ((t + 1) & 1) * STG_BYTES;
            const char* src = (const char*)g_nb + (t + 1) * STG_BYTES;
            for (int i = tid; i < 1152; i += 256) CPA16(dst + i*16, src + i*16);
        }
        if (t == 0) {         // Wv image into the weight region freed by GEMM0
            const char* sv = (const char*)g_wV;
            for (int i = tid; i < 1152; i += 256) CPA16(su + WH_B + i*16, sv + i*16);
        }
        CPA_COMMIT();
        const uint32_t sH = su + (t & 1) * STG_BYTES;
        const uint32_t sL = sH + 9216;

        // GEMM1: S = p @ nb^T
        float S[8][4];
        #pragma unroll
        for (int b = 0; b < 8; ++b)
            #pragma unroll
            for (int u = 0; u < 4; ++u) S[b][u] = 0.f;
        #pragma unroll
        for (int ks = 0; ks < 4; ++ks)
            #pragma unroll
            for (int P = 0; P < 4; ++P) {
                uint32_t off = ((16*P + rN)*STRD + 16*ks + cN) * 2;
                uint32_t bh[4], bl[4];
                LDSM4(bh[0], bh[1], bh[2], bh[3], sH + off);
                LDSM4(bl[0], bl[1], bl[2], bl[3], sL + off);
                MMA(S[2*P],   Ph[ks], bh);   MMA(S[2*P],   Pl[ks], bh);   MMA(S[2*P],   Ph[ks], bl);
                MMA(S[2*P+1], Ph[ks], bh+2); MMA(S[2*P+1], Pl[ks], bh+2); MMA(S[2*P+1], Ph[ks], bl+2);
            }

        // online softmax (rows g, g+8; reduce over 4 lanes)
        float mx0 = -1e30f, mx1 = -1e30f;
        #pragma unroll
        for (int b = 0; b < 8; ++b) {
            mx0 = fmaxf(mx0, fmaxf(S[b][0], S[b][1]));
            mx1 = fmaxf(mx1, fmaxf(S[b][2], S[b][3]));
        }
        mx0 = fmaxf(mx0, __shfl_xor_sync(0xFFFFFFFFu, mx0, 1));
        mx0 = fmaxf(mx0, __shfl_xor_sync(0xFFFFFFFFu, mx0, 2));
        mx1 = fmaxf(mx1, __shfl_xor_sync(0xFFFFFFFFu, mx1, 1));
        mx1 = fmaxf(mx1, __shfl_xor_sync(0xFFFFFFFFu, mx1, 2));
        float mn0 = fmaxf(mr0, mx0), mn1 = fmaxf(mr1, mx1);
        float sc0 = __expf(mr0 - mn0), sc1 = __expf(mr1 - mn1);
        mr0 = mn0; mr1 = mn1;
        float s0 = 0.f, s1 = 0.f;
        #pragma unroll
        for (int b = 0; b < 8; ++b) {
            S[b][0] = __expf(S[b][0] - mn0); s0 += S[b][0];
            S[b][1] = __expf(S[b][1] - mn0); s0 += S[b][1];
            S[b][2] = __expf(S[b][2] - mn1); s1 += S[b][2];
            S[b][3] = __expf(S[b][3] - mn1); s1 += S[b][3];
        }
        s0 += __shfl_xor_sync(0xFFFFFFFFu, s0, 1);
        s0 += __shfl_xor_sync(0xFFFFFFFFu, s0, 2);
        s1 += __shfl_xor_sync(0xFFFFFFFFu, s1, 1);
        s1 += __shfl_xor_sync(0xFFFFFFFFu, s1, 2);
        lr0 = lr0 * sc0 + s0;
        lr1 = lr1 * sc1 + s1;

        uint32_t Th[4][4], Tl[4][4];
        dfrag_to_afrag(S, 1.f, 1.f, Th, Tl);
        #pragma unroll
        for (int b = 0; b < 8; ++b) {
            ag[b][0] *= sc0; ag[b][1] *= sc0;
            ag[b][2] *= sc1; ag[b][3] *= sc1;
        }

        // GEMM2: ag += attn @ nb (trans B)
        #pragma unroll
        for (int ks = 0; ks < 4; ++ks)
            #pragma unroll
            for (int P = 0; P < 4; ++P) {
                uint32_t off = ((16*ks + rT)*STRD + 16*P + cT) * 2;
                uint32_t bh[4], bl[4];
                LDSM4T(bh[0], bh[1], bh[2], bh[3], sH + off);
                LDSM4T(bl[0], bl[1], bl[2], bl[3], sL + off);
                MMA(ag[2*P],   Th[ks], bh);   MMA(ag[2*P],   Tl[ks], bh);   MMA(ag[2*P],   Th[ks], bl);
                MMA(ag[2*P+1], Th[ks], bh+2); MMA(ag[2*P+1], Tl[ks], bh+2); MMA(ag[2*P+1], Th[ks], bl+2);
            }
    }

    // ---- epilogue: normalize -> A-frags; Wv image already resident; GEMM3; store ----
    float inv0 = 1.0f / lr0, inv1 = 1.0f / lr1;
    uint32_t Gh[4][4], Gl[4][4];
    dfrag_to_afrag(ag, inv0, inv1, Gh, Gl);
    if (tid < 64) bias[tid] = bv[tid];
    __syncthreads();
    float O[8][4];
    #pragma unroll
    for (int b = 0; b < 8; ++b) {
        O[b][0] = bias[8*b + 2*tg]; O[b][1] = bias[8*b + 2*tg + 1];
        O[b][2] = O[b][0];          O[b][3] = O[b][1];
    }
    #pragma unroll
    for (int ks = 0; ks < 4; ++ks)
        #pragma unroll
        for (int P = 0; P < 4; ++P) {
            uint32_t off = ((16*P + rN)*STRD + 16*ks + cN) * 2;
            uint32_t bh[4], bl[4];
            LDSM4(bh[0], bh[1], bh[2], bh[3], su + WH_B + off);
            LDSM4(bl[0], bl[1], bl[2], bl[3], su + WH_B + 9216 + off);
            MMA(O[2*P],   Gh[ks], bh);   MMA(O[2*P],   Gl[ks], bh);   MMA(O[2*P],   Gh[ks], bl);
            MMA(O[2*P+1], Gh[ks], bh+2); MMA(O[2*P+1], Gl[ks], bh+2); MMA(O[2*P+1], Gh[ks], bl+2);
        }
    #pragma unroll
    for (int b = 0; b < 8; ++b) {
        int col = 8*b + 2*tg;
        int row0 = n0 + m0 + g;
        if (row0 < N) *(float2*)&out[(size_t)row0*DI + col] = make_float2(O[b][0], O[b][1]);
        int row1 = row0 + 8;
        if (row1 < N) *(float2*)&out[(size_t)row1*DI + col] = make_float2(O[b][2], O[b][3]);
    }
}

extern "C" void kernel_launch(void* const* d_in, const int* in_sizes, int n_in,
                              void* d_out, int out_size) {
    const float* x  = (const float*)d_in[0];
    const float* nb = (const float*)d_in[1];
    const float* Wq = (const float*)d_in[2];
    const float* bq = (const float*)d_in[3];
    const float* Wk = (const float*)d_in[4];
    // d_in[5] = bk drops out of softmax
    const float* Wv = (const float*)d_in[6];
    const float* bv = (const float*)d_in[7];
    float* out = (float*)d_out;
    const int N = in_sizes[0] / DI;
    cudaFuncSetAttribute(gat_kernel, cudaFuncAttributeMaxDynamicSharedMemorySize, SM_BYTES);
    prep_A<<<16, 256>>>(Wq, bq, Wk);
    prep_img<<<288, 256>>>(nb, Wv);
    gat_kernel<<<(N + BR - 1) / BR, 256, SM_BYTES>>>(x, bv, out, N);
}

// round 9
// speedup vs baseline: 4.0822x; 1.1998x over previous
#include <cuda_runtime.h>
#include <cuda_fp16.h>
#include <cstdint>

#define DI 64
#define BR 128
#define STRD 72                 // halves per smem row (144B; conflict-free ldmatrix)
#define STG_BYTES 18432         // one stage: H image (9216B) + L image (9216B)
#define WH_B 36864              // weight image region (A, then Wv): H + L contiguous
#define BIAS_B 55296
#define SM_BYTES 55552

__device__ float g_bp[64];                        // bp[j] = (Wk^T bq)[j]
__device__ __align__(16) __half g_nb[16 * 9216];  // per tile: [hi 64x72 | lo 64x72]
__device__ __align__(16) __half g_wA[9216];       // A image  [hi 64x72 | lo 64x72]
__device__ __align__(16) __half g_wV[9216];       // Wv image

static __device__ __forceinline__ uint32_t smem_u32(const void* p) {
    uint32_t a;
    asm("{.reg .u64 t; cvta.to.shared.u64 t,%1; cvt.u32.u64 %0,t;}" : "=r"(a) : "l"(p));
    return a;
}
#define LDSM4(r0,r1,r2,r3,a) asm volatile("ldmatrix.sync.aligned.m8n8.x4.shared.b16 {%0,%1,%2,%3},[%4];" \
    : "=r"(r0),"=r"(r1),"=r"(r2),"=r"(r3) : "r"(a))
#define LDSM4T(r0,r1,r2,r3,a) asm volatile("ldmatrix.sync.aligned.m8n8.x4.trans.shared.b16 {%0,%1,%2,%3},[%4];" \
    : "=r"(r0),"=r"(r1),"=r"(r2),"=r"(r3) : "r"(a))
#define MMA(d,a,b) asm volatile( \
    "mma.sync.aligned.m16n8k16.row.col.f32.f16.f16.f32 {%0,%1,%2,%3},{%4,%5,%6,%7},{%8,%9},{%0,%1,%2,%3};" \
    : "+f"((d)[0]),"+f"((d)[1]),"+f"((d)[2]),"+f"((d)[3]) \
    : "r"((a)[0]),"r"((a)[1]),"r"((a)[2]),"r"((a)[3]),"r"((b)[0]),"r"((b)[1]))
#define CPA16(dst, src)  asm volatile("cp.async.ca.shared.global [%0],[%1],16;" :: "r"(dst), "l"(src))
#define CPA_COMMIT()     asm volatile("cp.async.commit_group;" ::: "memory")
#define CPA_WAIT0()      asm volatile("cp.async.wait_group 0;" ::: "memory")

static __device__ __forceinline__ uint32_t h2pack(__half a, __half b) {
    return (uint32_t)__half_as_ushort(b) << 16 | (uint32_t)__half_as_ushort(a);
}
static __device__ __forceinline__ void split2(float x, float y, uint32_t& hi, uint32_t& lo) {
    __half hx = __float2half_rn(x), hy = __float2half_rn(y);
    __half lx = __float2half_rn(x - __half2float(hx));
    __half ly = __float2half_rn(y - __half2float(hy));
    hi = h2pack(hx, hy);
    lo = h2pack(lx, ly);
}
// D-frag (8 n-blocks x 4) -> hi/lo A-frags over k (4 ksteps x 4) with per-row scales
static __device__ __forceinline__ void dfrag_to_afrag(const float D[8][4], float s0, float s1,
                                                      uint32_t Ah[4][4], uint32_t Al[4][4]) {
    #pragma unroll
    for (int ks = 0; ks < 4; ++ks) {
        split2(D[2*ks][0]*s0,   D[2*ks][1]*s0,   Ah[ks][0], Al[ks][0]);
        split2(D[2*ks][2]*s1,   D[2*ks][3]*s1,   Ah[ks][1], Al[ks][1]);
        split2(D[2*ks+1][0]*s0, D[2*ks+1][1]*s0, Ah[ks][2], Al[ks][2]);
        split2(D[2*ks+1][2]*s1, D[2*ks+1][3]*s1, Ah[ks][3], Al[ks][3]);
    }
}
// hi-only variant (for attn -> GEMM2, lo pass dropped)
static __device__ __forceinline__ void dfrag_to_afrag_hi(const float D[8][4], uint32_t Ah[4][4]) {
    #pragma unroll
    for (int ks = 0; ks < 4; ++ks) {
        Ah[ks][0] = h2pack(__float2half_rn(D[2*ks][0]),   __float2half_rn(D[2*ks][1]));
        Ah[ks][1] = h2pack(__float2half_rn(D[2*ks][2]),   __float2half_rn(D[2*ks][3]));
        Ah[ks][2] = h2pack(__float2half_rn(D[2*ks+1][0]), __float2half_rn(D[2*ks+1][1]));
        Ah[ks][3] = h2pack(__float2half_rn(D[2*ks+1][2]), __float2half_rn(D[2*ks+1][3]));
    }
}

// ONE prep kernel, grid 288 x 256:
//   blocks 0-255:  nb -> hi/lo ldmatrix images
//   blocks 256-271: A[j][d] = (Wk^T Wq)[j][d] computed inline -> hi/lo image; b 256 also bp
//   blocks 272-287: Wv -> hi/lo image
__global__ void prep(const float* __restrict__ Wq, const float* __restrict__ bq,
                     const float* __restrict__ Wk, const float* __restrict__ nb,
                     const float* __restrict__ Wv) {
    int b = blockIdx.x;
    if (b < 256) {
        int idx = b * 256 + threadIdx.x;          // 65536
        int row = idx >> 6, d = idx & 63;
        int t = row >> 6, j = row & 63;
        float v = nb[idx];
        __half h = __float2half_rn(v);
        __half l = __float2half_rn(v - __half2float(h));
        g_nb[t*9216 + j*STRD + d] = h;
        g_nb[t*9216 + 4608 + j*STRD + d] = l;
    } else if (b < 272) {
        int idx = (b - 256) * 256 + threadIdx.x;  // 4096
        int j = idx >> 6, d = idx & 63;
        float s = 0.f;
        #pragma unroll 8
        for (int t = 0; t < 64; ++t) s += Wk[t*64 + j] * Wq[t*64 + d];
        __half h = __float2half_rn(s);
        __half l = __float2half_rn(s - __half2float(h));
        g_wA[j*STRD + d] = h;
        g_wA[4608 + j*STRD + d] = l;
        if (b == 256 && threadIdx.x < 64) {
            int jj = threadIdx.x;
            float bb = 0.f;
            #pragma unroll 8
            for (int t = 0; t < 64; ++t) bb += Wk[t*64 + jj] * bq[t];
            g_bp[jj] = bb;
        }
    } else {
        int idx = (b - 272) * 256 + threadIdx.x;  // 4096
        int o = idx >> 6, e = idx & 63;
        float v = Wv[idx];
        __half h = __float2half_rn(v);
        __half l = __float2half_rn(v - __half2float(h));
        g_wV[o*STRD + e] = h;
        g_wV[4608 + o*STRD + e] = l;
    }
}

__global__ void __launch_bounds__(256, 2)
gat_kernel(const float* __restrict__ x, const float* __restrict__ bv,
           float* __restrict__ out, int N) {
    extern __shared__ char sm[];
    const uint32_t su = smem_u32(sm);
    const int tid = threadIdx.x, lane = tid & 31, wid = tid >> 5;
    const int g = lane >> 2, tg = lane & 3;
    const int m0 = wid * 16;
    const int n0 = blockIdx.x * BR;
    float* bias = (float*)(sm + BIAS_B);

    const int rN = ((lane >> 4) & 1) * 8 + (lane & 7);
    const int cN = ((lane >> 3) & 1) * 8;
    const int rT = ((lane >> 3) & 1) * 8 + (lane & 7);
    const int cT = ((lane >> 4) & 1) * 8;

    // ---- start tile-0 + A-image copies immediately ----
    {
        const char* s0 = (const char*)g_nb;
        const char* sa = (const char*)g_wA;
        for (int i = tid; i < 1152; i += 256) {
            CPA16(su + i*16, s0 + i*16);
            CPA16(su + WH_B + i*16, sa + i*16);
        }
        CPA_COMMIT();
    }
    if (tid < 64) bias[tid] = g_bp[tid];

    // ---- x fragments straight from global ----
    uint32_t Xh[4][4], Xl[4][4];
    {
        int r0 = n0 + m0 + g, r1 = r0 + 8;
        #pragma unroll
        for (int q = 0; q < 8; ++q) {
            int c = 2*tg + 8*q;
            float2 v0 = make_float2(0.f, 0.f), v1 = make_float2(0.f, 0.f);
            if (r0 < N) v0 = *(const float2*)&x[(size_t)r0*DI + c];
            if (r1 < N) v1 = *(const float2*)&x[(size_t)r1*DI + c];
            int ks = q >> 1;
            if ((q & 1) == 0) {
                split2(v0.x, v0.y, Xh[ks][0], Xl[ks][0]);
                split2(v1.x, v1.y, Xh[ks][1], Xl[ks][1]);
            } else {
                split2(v0.x, v0.y, Xh[ks][2], Xl[ks][2]);
                split2(v1.x, v1.y, Xh[ks][3], Xl[ks][3]);
            }
        }
    }
    CPA_WAIT0();
    __syncthreads();

    // ---- GEMM0: p = x @ A^T + bp (3-pass, precision-critical) ----
    float D[8][4];
    #pragma unroll
    for (int b = 0; b < 8; ++b) {
        D[b][0] = bias[8*b + 2*tg]; D[b][1] = bias[8*b + 2*tg + 1];
        D[b][2] = D[b][0];          D[b][3] = D[b][1];
    }
    #pragma unroll
    for (int ks = 0; ks < 4; ++ks)
        #pragma unroll
        for (int P = 0; P < 4; ++P) {
            uint32_t off = ((16*P + rN)*STRD + 16*ks + cN) * 2;
            uint32_t bh[4], bl[4];
            LDSM4(bh[0], bh[1], bh[2], bh[3], su + WH_B + off);
            LDSM4(bl[0], bl[1], bl[2], bl[3], su + WH_B + 9216 + off);
            MMA(D[2*P],   Xh[ks], bh);     MMA(D[2*P],   Xl[ks], bh);     MMA(D[2*P],   Xh[ks], bl);
            MMA(D[2*P+1], Xh[ks], bh+2);   MMA(D[2*P+1], Xl[ks], bh+2);   MMA(D[2*P+1], Xh[ks], bl+2);
        }
    uint32_t Ph[4][4], Pl[4][4];
    dfrag_to_afrag(D, 1.f, 1.f, Ph, Pl);

    // ---- flash loop (double-buffered nb stages) ----
    float ag[8][4];
    #pragma unroll
    for (int b = 0; b < 8; ++b)
        #pragma unroll
        for (int u = 0; u < 4; ++u) ag[b][u] = 0.f;
    float mr0 = -1e30f, mr1 = -1e30f, lr0 = 0.f, lr1 = 0.f;

    for (int t = 0; t < 16; ++t) {
        CPA_WAIT0();
        __syncthreads();
        if (t + 1 < 16) {
            uint32_t dst = su + ((t + 1) & 1) * STG_BYTES;
            const char* src = (const char*)g_nb + (t + 1) * STG_BYTES;
            for (int i = tid; i < 1152; i += 256) CPA16(dst + i*16, src + i*16);
        }
        if (t == 0) {   // Wv image into weight region freed by GEMM0
            const char* sv = (const char*)g_wV;
            for (int i = tid; i < 1152; i += 256) CPA16(su + WH_B + i*16, sv + i*16);
        }
        CPA_COMMIT();
        const uint32_t sH = su + (t & 1) * STG_BYTES;
        const uint32_t sL = sH + 9216;

        // GEMM1: S = p @ nb^T (3-pass: logit precision drives softmax)
        float S[8][4];
        #pragma unroll
        for (int b = 0; b < 8; ++b)
            #pragma unroll
            for (int u = 0; u < 4; ++u) S[b][u] = 0.f;
        #pragma unroll
        for (int ks = 0; ks < 4; ++ks)
            #pragma unroll
            for (int P = 0; P < 4; ++P) {
                uint32_t off = ((16*P + rN)*STRD + 16*ks + cN) * 2;
                uint32_t bh[4], bl[4];
                LDSM4(bh[0], bh[1], bh[2], bh[3], sH + off);
                LDSM4(bl[0], bl[1], bl[2], bl[3], sL + off);
                MMA(S[2*P],   Ph[ks], bh);   MMA(S[2*P],   Pl[ks], bh);   MMA(S[2*P],   Ph[ks], bl);
                MMA(S[2*P+1], Ph[ks], bh+2); MMA(S[2*P+1], Pl[ks], bh+2); MMA(S[2*P+1], Ph[ks], bl+2);
            }

        // online softmax
        float mx0 = -1e30f, mx1 = -1e30f;
        #pragma unroll
        for (int b = 0; b < 8; ++b) {
            mx0 = fmaxf(mx0, fmaxf(S[b][0], S[b][1]));
            mx1 = fmaxf(mx1, fmaxf(S[b][2], S[b][3]));
        }
        mx0 = fmaxf(mx0, __shfl_xor_sync(0xFFFFFFFFu, mx0, 1));
        mx0 = fmaxf(mx0, __shfl_xor_sync(0xFFFFFFFFu, mx0, 2));
        mx1 = fmaxf(mx1, __shfl_xor_sync(0xFFFFFFFFu, mx1, 1));
        mx1 = fmaxf(mx1, __shfl_xor_sync(0xFFFFFFFFu, mx1, 2));
        float mn0 = fmaxf(mr0, mx0), mn1 = fmaxf(mr1, mx1);
        float sc0 = __expf(mr0 - mn0), sc1 = __expf(mr1 - mn1);
        mr0 = mn0; mr1 = mn1;
        float s0 = 0.f, s1 = 0.f;
        #pragma unroll
        for (int b = 0; b < 8; ++b) {
            S[b][0] = __expf(S[b][0] - mn0); s0 += S[b][0];
            S[b][1] = __expf(S[b][1] - mn0); s0 += S[b][1];
            S[b][2] = __expf(S[b][2] - mn1); s1 += S[b][2];
            S[b][3] = __expf(S[b][3] - mn1); s1 += S[b][3];
        }
        s0 += __shfl_xor_sync(0xFFFFFFFFu, s0, 1);
        s0 += __shfl_xor_sync(0xFFFFFFFFu, s0, 2);
        s1 += __shfl_xor_sync(0xFFFFFFFFu, s1, 1);
        s1 += __shfl_xor_sync(0xFFFFFFFFu, s1, 2);
        lr0 = lr0 * sc0 + s0;
        lr1 = lr1 * sc1 + s1;

        uint32_t Th[4][4];
        dfrag_to_afrag_hi(S, Th);
        #pragma unroll
        for (int b = 0; b < 8; ++b) {
            ag[b][0] *= sc0; ag[b][1] *= sc0;
            ag[b][2] *= sc1; ag[b][3] *= sc1;
        }

        // GEMM2: ag += attn @ nb (2-pass: attn-hi x nb-hi + attn-hi x nb-lo)
        #pragma unroll
        for (int ks = 0; ks < 4; ++ks)
            #pragma unroll
            for (int P = 0; P < 4; ++P) {
                uint32_t off = ((16*ks + rT)*STRD + 16*P + cT) * 2;
                uint32_t bh[4], bl[4];
                LDSM4T(bh[0], bh[1], bh[2], bh[3], sH + off);
                LDSM4T(bl[0], bl[1], bl[2], bl[3], sL + off);
                MMA(ag[2*P],   Th[ks], bh);   MMA(ag[2*P],   Th[ks], bl);
                MMA(ag[2*P+1], Th[ks], bh+2); MMA(ag[2*P+1], Th[ks], bl+2);
            }
    }

    // ---- epilogue: normalize -> A-frags; GEMM3 (3-pass); store ----
    float inv0 = 1.0f / lr0, inv1 = 1.0f / lr1;
    uint32_t Gh[4][4], Gl[4][4];
    dfrag_to_afrag(ag, inv0, inv1, Gh, Gl);
    if (tid < 64) bias[tid] = bv[tid];
    __syncthreads();
    float O[8][4];
    #pragma unroll
    for (int b = 0; b < 8; ++b) {
        O[b][0] = bias[8*b + 2*tg]; O[b][1] = bias[8*b + 2*tg + 1];
        O[b][2] = O[b][0];          O[b][3] = O[b][1];
    }
    #pragma unroll
    for (int ks = 0; ks < 4; ++ks)
        #pragma unroll
        for (int P = 0; P < 4; ++P) {
            uint32_t off = ((16*P + rN)*STRD + 16*ks + cN) * 2;
            uint32_t bh[4], bl[4];
            LDSM4(bh[0], bh[1], bh[2], bh[3], su + WH_B + off);
            LDSM4(bl[0], bl[1], bl[2], bl[3], su + WH_B + 9216 + off);
            MMA(O[2*P],   Gh[ks], bh);   MMA(O[2*P],   Gl[ks], bh);   MMA(O[2*P],   Gh[ks], bl);
            MMA(O[2*P+1], Gh[ks], bh+2); MMA(O[2*P+1], Gl[ks], bh+2); MMA(O[2*P+1], Gh[ks], bl+2);
        }
    #pragma unroll
    for (int b = 0; b < 8; ++b) {
        int col = 8*b + 2*tg;
        int row0 = n0 + m0 + g;
        if (row0 < N) *(float2*)&out[(size_t)row0*DI + col] = make_float2(O[b][0], O[b][1]);
        int row1 = row0 + 8;
        if (row1 < N) *(float2*)&out[(size_t)row1*DI + col] = make_float2(O[b][2], O[b][3]);
    }
}

extern "C" void kernel_launch(void* const* d_in, const int* in_sizes, int n_in,
                              void* d_out, int out_size) {
    const float* x  = (const float*)d_in[0];
    const float* nb = (const float*)d_in[1];
    const float* Wq = (const float*)d_in[2];
    const float* bq = (const float*)d_in[3];
    const float* Wk = (const float*)d_in[4];
    // d_in[5] = bk drops out of softmax
    const float* Wv = (const float*)d_in[6];
    const float* bv = (const float*)d_in[7];
    float* out = (float*)d_out;
    const int N = in_sizes[0] / DI;
    cudaFuncSetAttribute(gat_kernel, cudaFuncAttributeMaxDynamicSharedMemorySize, SM_BYTES);
    prep<<<288, 256>>>(Wq, bq, Wk, nb, Wv);
    gat_kernel<<<(N + BR - 1) / BR, 256, SM_BYTES>>>(x, bv, out, N);
}

// round 10
// speedup vs baseline: 4.7372x; 1.1605x over previous
#include <cuda_runtime.h>
#include <cuda_fp16.h>
#include <cstdint>

#define DI 64
#define BR 128
#define STRD 72                 // halves per smem row (144B; conflict-free ldmatrix)
#define STG_BYTES 18432         // one stage: H image (9216B) + L image (9216B)
#define WH_B 36864              // weight image region (A, then Wv): H + L contiguous
#define BIAS_B 55296
#define SM_BYTES 55552

__device__ float g_bp[64];                        // bp[j] = (Wk^T bq)[j]
__device__ __align__(16) __half g_nb[16 * 9216];  // per tile: [hi 64x72 | lo 64x72]
__device__ __align__(16) __half g_wA[9216];       // A image  [hi 64x72 | lo 64x72]
__device__ __align__(16) __half g_wV[9216];       // Wv image

static __device__ __forceinline__ uint32_t smem_u32(const void* p) {
    uint32_t a;
    asm("{.reg .u64 t; cvta.to.shared.u64 t,%1; cvt.u32.u64 %0,t;}" : "=r"(a) : "l"(p));
    return a;
}
#define LDSM4(r0,r1,r2,r3,a) asm volatile("ldmatrix.sync.aligned.m8n8.x4.shared.b16 {%0,%1,%2,%3},[%4];" \
    : "=r"(r0),"=r"(r1),"=r"(r2),"=r"(r3) : "r"(a))
#define LDSM4T(r0,r1,r2,r3,a) asm volatile("ldmatrix.sync.aligned.m8n8.x4.trans.shared.b16 {%0,%1,%2,%3},[%4];" \
    : "=r"(r0),"=r"(r1),"=r"(r2),"=r"(r3) : "r"(a))
#define MMA(d,a,b) asm volatile( \
    "mma.sync.aligned.m16n8k16.row.col.f32.f16.f16.f32 {%0,%1,%2,%3},{%4,%5,%6,%7},{%8,%9},{%0,%1,%2,%3};" \
    : "+f"((d)[0]),"+f"((d)[1]),"+f"((d)[2]),"+f"((d)[3]) \
    : "r"((a)[0]),"r"((a)[1]),"r"((a)[2]),"r"((a)[3]),"r"((b)[0]),"r"((b)[1]))
#define CPA16(dst, src)  asm volatile("cp.async.cg.shared.global [%0],[%1],16;" :: "r"(dst), "l"(src))
#define CPA_COMMIT()     asm volatile("cp.async.commit_group;" ::: "memory")
#define CPA_WAIT0()      asm volatile("cp.async.wait_group 0;" ::: "memory")

static __device__ __forceinline__ uint32_t h2pack(__half a, __half b) {
    return (uint32_t)__half_as_ushort(b) << 16 | (uint32_t)__half_as_ushort(a);
}
static __device__ __forceinline__ void split2(float x, float y, uint32_t& hi, uint32_t& lo) {
    __half hx = __float2half_rn(x), hy = __float2half_rn(y);
    __half lx = __float2half_rn(x - __half2float(hx));
    __half ly = __float2half_rn(y - __half2float(hy));
    hi = h2pack(hx, hy);
    lo = h2pack(lx, ly);
}
// D-frag (8 n-blocks x 4) -> hi/lo A-frags over k (4 ksteps x 4) with per-row scales
static __device__ __forceinline__ void dfrag_to_afrag(const float D[8][4], float s0, float s1,
                                                      uint32_t Ah[4][4], uint32_t Al[4][4]) {
    #pragma unroll
    for (int ks = 0; ks < 4; ++ks) {
        split2(D[2*ks][0]*s0,   D[2*ks][1]*s0,   Ah[ks][0], Al[ks][0]);
        split2(D[2*ks][2]*s1,   D[2*ks][3]*s1,   Ah[ks][1], Al[ks][1]);
        split2(D[2*ks+1][0]*s0, D[2*ks+1][1]*s0, Ah[ks][2], Al[ks][2]);
        split2(D[2*ks+1][2]*s1, D[2*ks+1][3]*s1, Ah[ks][3], Al[ks][3]);
    }
}
// hi-only variant (for attn -> GEMM2)
static __device__ __forceinline__ void dfrag_to_afrag_hi(const float D[8][4], uint32_t Ah[4][4]) {
    #pragma unroll
    for (int ks = 0; ks < 4; ++ks) {
        Ah[ks][0] = h2pack(__float2half_rn(D[2*ks][0]),   __float2half_rn(D[2*ks][1]));
        Ah[ks][1] = h2pack(__float2half_rn(D[2*ks][2]),   __float2half_rn(D[2*ks][3]));
        Ah[ks][2] = h2pack(__float2half_rn(D[2*ks+1][0]), __float2half_rn(D[2*ks+1][1]));
        Ah[ks][3] = h2pack(__float2half_rn(D[2*ks+1][2]), __float2half_rn(D[2*ks+1][3]));
    }
}

// ONE prep kernel, grid 288 x 256:
//   blocks 0-255:  nb -> hi/lo ldmatrix images
//   blocks 256-271: A[j][d] = (Wk^T Wq)[j][d] computed inline -> hi/lo image; b 256 also bp
//   blocks 272-287: Wv -> hi/lo image
__global__ void prep(const float* __restrict__ Wq, const float* __restrict__ bq,
                     const float* __restrict__ Wk, const float* __restrict__ nb,
                     const float* __restrict__ Wv) {
    int b = blockIdx.x;
    if (b < 256) {
        int idx = b * 256 + threadIdx.x;          // 65536
        int row = idx >> 6, d = idx & 63;
        int t = row >> 6, j = row & 63;
        float v = nb[idx];
        __half h = __float2half_rn(v);
        __half l = __float2half_rn(v - __half2float(h));
        g_nb[t*9216 + j*STRD + d] = h;
        g_nb[t*9216 + 4608 + j*STRD + d] = l;
    } else if (b < 272) {
        int idx = (b - 256) * 256 + threadIdx.x;  // 4096
        int j = idx >> 6, d = idx & 63;
        float s = 0.f;
        #pragma unroll 8
        for (int t = 0; t < 64; ++t) s += Wk[t*64 + j] * Wq[t*64 + d];
        __half h = __float2half_rn(s);
        __half l = __float2half_rn(s - __half2float(h));
        g_wA[j*STRD + d] = h;
        g_wA[4608 + j*STRD + d] = l;
        if (b == 256 && threadIdx.x < 64) {
            int jj = threadIdx.x;
            float bb = 0.f;
            #pragma unroll 8
            for (int t = 0; t < 64; ++t) bb += Wk[t*64 + jj] * bq[t];
            g_bp[jj] = bb;
        }
    } else {
        int idx = (b - 272) * 256 + threadIdx.x;  // 4096
        int o = idx >> 6, e = idx & 63;
        float v = Wv[idx];
        __half h = __float2half_rn(v);
        __half l = __float2half_rn(v - __half2float(h));
        g_wV[o*STRD + e] = h;
        g_wV[4608 + o*STRD + e] = l;
    }
}

__global__ void __launch_bounds__(256, 2)
gat_kernel(const float* __restrict__ x, const float* __restrict__ bv,
           float* __restrict__ out, int N) {
    extern __shared__ char sm[];
    const uint32_t su = smem_u32(sm);
    const int tid = threadIdx.x, lane = tid & 31, wid = tid >> 5;
    const int g = lane >> 2, tg = lane & 3;
    const int m0 = wid * 16;
    const int n0 = blockIdx.x * BR;
    float* bias = (float*)(sm + BIAS_B);

    const int rN = ((lane >> 4) & 1) * 8 + (lane & 7);
    const int cN = ((lane >> 3) & 1) * 8;
    const int rT = ((lane >> 3) & 1) * 8 + (lane & 7);
    const int cT = ((lane >> 4) & 1) * 8;

    // ---- start tile-0 + A-image copies immediately ----
    {
        const char* s0 = (const char*)g_nb;
        const char* sa = (const char*)g_wA;
        for (int i = tid; i < 1152; i += 256) {
            CPA16(su + i*16, s0 + i*16);
            CPA16(su + WH_B + i*16, sa + i*16);
        }
        CPA_COMMIT();
    }
    if (tid < 64) bias[tid] = g_bp[tid];

    // ---- x fragments straight from global ----
    uint32_t Xh[4][4], Xl[4][4];
    {
        int r0 = n0 + m0 + g, r1 = r0 + 8;
        #pragma unroll
        for (int q = 0; q < 8; ++q) {
            int c = 2*tg + 8*q;
            float2 v0 = make_float2(0.f, 0.f), v1 = make_float2(0.f, 0.f);
            if (r0 < N) v0 = *(const float2*)&x[(size_t)r0*DI + c];
            if (r1 < N) v1 = *(const float2*)&x[(size_t)r1*DI + c];
            int ks = q >> 1;
            if ((q & 1) == 0) {
                split2(v0.x, v0.y, Xh[ks][0], Xl[ks][0]);
                split2(v1.x, v1.y, Xh[ks][1], Xl[ks][1]);
            } else {
                split2(v0.x, v0.y, Xh[ks][2], Xl[ks][2]);
                split2(v1.x, v1.y, Xh[ks][3], Xl[ks][3]);
            }
        }
    }
    CPA_WAIT0();
    __syncthreads();

    // ---- GEMM0: p = x @ A^T + bp (3-pass, precision-critical) ----
    float D[8][4];
    #pragma unroll
    for (int b = 0; b < 8; ++b) {
        D[b][0] = bias[8*b + 2*tg]; D[b][1] = bias[8*b + 2*tg + 1];
        D[b][2] = D[b][0];          D[b][3] = D[b][1];
    }
    #pragma unroll
    for (int ks = 0; ks < 4; ++ks)
        #pragma unroll
        for (int P = 0; P < 4; ++P) {
            uint32_t off = ((16*P + rN)*STRD + 16*ks + cN) * 2;
            uint32_t bh[4], bl[4];
            LDSM4(bh[0], bh[1], bh[2], bh[3], su + WH_B + off);
            LDSM4(bl[0], bl[1], bl[2], bl[3], su + WH_B + 9216 + off);
            MMA(D[2*P],   Xh[ks], bh);     MMA(D[2*P],   Xl[ks], bh);     MMA(D[2*P],   Xh[ks], bl);
            MMA(D[2*P+1], Xh[ks], bh+2);   MMA(D[2*P+1], Xl[ks], bh+2);   MMA(D[2*P+1], Xh[ks], bl+2);
        }
    uint32_t Ph[4][4], Pl[4][4];
    dfrag_to_afrag(D, 1.f, 1.f, Ph, Pl);

    // ---- flash loop (double-buffered nb stages) ----
    float ag[8][4];
    #pragma unroll
    for (int b = 0; b < 8; ++b)
        #pragma unroll
        for (int u = 0; u < 4; ++u) ag[b][u] = 0.f;
    float mr0 = -1e30f, mr1 = -1e30f, lr0 = 0.f, lr1 = 0.f;

    for (int t = 0; t < 16; ++t) {
        CPA_WAIT0();
        __syncthreads();
        if (t + 1 < 16) {
            uint32_t dst = su + ((t + 1) & 1) * STG_BYTES;
            const char* src = (const char*)g_nb + (t + 1) * STG_BYTES;
            for (int i = tid; i < 1152; i += 256) CPA16(dst + i*16, src + i*16);
        }
        if (t == 0) {   // Wv image into weight region freed by GEMM0
            const char* sv = (const char*)g_wV;
            for (int i = tid; i < 1152; i += 256) CPA16(su + WH_B + i*16, sv + i*16);
        }
        CPA_COMMIT();
        const uint32_t sH = su + (t & 1) * STG_BYTES;
        const uint32_t sL = sH + 9216;

        // GEMM1: S = p @ nb^T (3-pass: logit precision drives softmax)
        float S[8][4];
        #pragma unroll
        for (int b = 0; b < 8; ++b)
            #pragma unroll
            for (int u = 0; u < 4; ++u) S[b][u] = 0.f;
        #pragma unroll
        for (int ks = 0; ks < 4; ++ks)
            #pragma unroll
            for (int P = 0; P < 4; ++P) {
                uint32_t off = ((16*P + rN)*STRD + 16*ks + cN) * 2;
                uint32_t bh[4], bl[4];
                LDSM4(bh[0], bh[1], bh[2], bh[3], sH + off);
                LDSM4(bl[0], bl[1], bl[2], bl[3], sL + off);
                MMA(S[2*P],   Ph[ks], bh);   MMA(S[2*P],   Pl[ks], bh);   MMA(S[2*P],   Ph[ks], bl);
                MMA(S[2*P+1], Ph[ks], bh+2); MMA(S[2*P+1], Pl[ks], bh+2); MMA(S[2*P+1], Ph[ks], bl+2);
            }

        // online softmax
        float mx0 = -1e30f, mx1 = -1e30f;
        #pragma unroll
        for (int b = 0; b < 8; ++b) {
            mx0 = fmaxf(mx0, fmaxf(S[b][0], S[b][1]));
            mx1 = fmaxf(mx1, fmaxf(S[b][2], S[b][3]));
        }
        mx0 = fmaxf(mx0, __shfl_xor_sync(0xFFFFFFFFu, mx0, 1));
        mx0 = fmaxf(mx0, __shfl_xor_sync(0xFFFFFFFFu, mx0, 2));
        mx1 = fmaxf(mx1, __shfl_xor_sync(0xFFFFFFFFu, mx1, 1));
        mx1 = fmaxf(mx1, __shfl_xor_sync(0xFFFFFFFFu, mx1, 2));
        float mn0 = fmaxf(mr0, mx0), mn1 = fmaxf(mr1, mx1);
        float sc0 = __expf(mr0 - mn0), sc1 = __expf(mr1 - mn1);
        mr0 = mn0; mr1 = mn1;
        float s0 = 0.f, s1 = 0.f;
        #pragma unroll
        for (int b = 0; b < 8; ++b) {
            S[b][0] = __expf(S[b][0] - mn0); s0 += S[b][0];
            S[b][1] = __expf(S[b][1] - mn0); s0 += S[b][1];
            S[b][2] = __expf(S[b][2] - mn1); s1 += S[b][2];
            S[b][3] = __expf(S[b][3] - mn1); s1 += S[b][3];
        }
        s0 += __shfl_xor_sync(0xFFFFFFFFu, s0, 1);
        s0 += __shfl_xor_sync(0xFFFFFFFFu, s0, 2);
        s1 += __shfl_xor_sync(0xFFFFFFFFu, s1, 1);
        s1 += __shfl_xor_sync(0xFFFFFFFFu, s1, 2);
        lr0 = lr0 * sc0 + s0;
        lr1 = lr1 * sc1 + s1;

        uint32_t Th[4][4];
        dfrag_to_afrag_hi(S, Th);
        #pragma unroll
        for (int b = 0; b < 8; ++b) {
            ag[b][0] *= sc0; ag[b][1] *= sc0;
            ag[b][2] *= sc1; ag[b][3] *= sc1;
        }

        // GEMM2: ag += attn @ nb (single pass: attn-hi x nb-hi)
        #pragma unroll
        for (int ks = 0; ks < 4; ++ks)
            #pragma unroll
            for (int P = 0; P < 4; ++P) {
                uint32_t off = ((16*ks + rT)*STRD + 16*P + cT) * 2;
                uint32_t bh[4];
                LDSM4T(bh[0], bh[1], bh[2], bh[3], sH + off);
                MMA(ag[2*P],   Th[ks], bh);
                MMA(ag[2*P+1], Th[ks], bh+2);
            }
    }

    // ---- epilogue: normalize -> A-frags; GEMM3 (3-pass); store ----
    float inv0 = 1.0f / lr0, inv1 = 1.0f / lr1;
    uint32_t Gh[4][4], Gl[4][4];
    dfrag_to_afrag(ag, inv0, inv1, Gh, Gl);
    if (tid < 64) bias[tid] = bv[tid];
    __syncthreads();
    float O[8][4];
    #pragma unroll
    for (int b = 0; b < 8; ++b) {
        O[b][0] = bias[8*b + 2*tg]; O[b][1] = bias[8*b + 2*tg + 1];
        O[b][2] = O[b][0];          O[b][3] = O[b][1];
    }
    #pragma unroll
    for (int ks = 0; ks < 4; ++ks)
        #pragma unroll
        for (int P = 0; P < 4; ++P) {
            uint32_t off = ((16*P + rN)*STRD + 16*ks + cN) * 2;
            uint32_t bh[4], bl[4];
            LDSM4(bh[0], bh[1], bh[2], bh[3], su + WH_B + off);
            LDSM4(bl[0], bl[1], bl[2], bl[3], su + WH_B + 9216 + off);
            MMA(O[2*P],   Gh[ks], bh);   MMA(O[2*P],   Gl[ks], bh);   MMA(O[2*P],   Gh[ks], bl);
            MMA(O[2*P+1], Gh[ks], bh+2); MMA(O[2*P+1], Gl[ks], bh+2); MMA(O[2*P+1], Gh[ks], bl+2);
        }
    #pragma unroll
    for (int b = 0; b < 8; ++b) {
        int col = 8*b + 2*tg;
        int row0 = n0 + m0 + g;
        if (row0 < N) *(float2*)&out[(size_t)row0*DI + col] = make_float2(O[b][0], O[b][1]);
        int row1 = row0 + 8;
        if (row1 < N) *(float2*)&out[(size_t)row1*DI + col] = make_float2(O[b][2], O[b][3]);
    }
}

extern "C" void kernel_launch(void* const* d_in, const int* in_sizes, int n_in,
                              void* d_out, int out_size) {
    const float* x  = (const float*)d_in[0];
    const float* nb = (const float*)d_in[1];
    const float* Wq = (const float*)d_in[2];
    const float* bq = (const float*)d_in[3];
    const float* Wk = (const float*)d_in[4];
    // d_in[5] = bk drops out of softmax
    const float* Wv = (const float*)d_in[6];
    const float* bv = (const float*)d_in[7];
    float* out = (float*)d_out;
    const int N = in_sizes[0] / DI;
    cudaFuncSetAttribute(gat_kernel, cudaFuncAttributeMaxDynamicSharedMemorySize, SM_BYTES);
    prep<<<288, 256>>>(Wq, bq, Wk, nb, Wv);
    gat_kernel<<<(N + BR - 1) / BR, 256, SM_BYTES>>>(x, bv, out, N);
}

// round 11
// speedup vs baseline: 5.3816x; 1.1360x over previous
#include <cuda_runtime.h>
#include <cuda_fp16.h>
#include <cstdint>

#define DI 64
#define BR 64                   // rows per CTA (4 warps x 16)
#define NTHR 128
#define STRD 72                 // halves per smem row (144B; conflict-free ldmatrix)
#define STG_BYTES 18432         // one stage: H image (9216B) + L image (9216B)
#define WH_B 36864              // weight image region (A, then Wv): H + L contiguous
#define BIAS_B 55296
#define SM_BYTES 55552

__device__ float g_bp[64];                        // log2(e) * (Wk^T bq)[j]
__device__ __align__(16) __half g_nb[16 * 9216];  // per tile: [hi 64x72 | lo 64x72]
__device__ __align__(16) __half g_wA[9216];       // A image (scaled by log2e)
__device__ __align__(16) __half g_wV[9216];       // Wv image

static __device__ __forceinline__ uint32_t smem_u32(const void* p) {
    uint32_t a;
    asm("{.reg .u64 t; cvta.to.shared.u64 t,%1; cvt.u32.u64 %0,t;}" : "=r"(a) : "l"(p));
    return a;
}
static __device__ __forceinline__ float ex2f(float x) {
    float y; asm("ex2.approx.f32 %0,%1;" : "=f"(y) : "f"(x)); return y;
}
#define LDSM4(r0,r1,r2,r3,a) asm volatile("ldmatrix.sync.aligned.m8n8.x4.shared.b16 {%0,%1,%2,%3},[%4];" \
    : "=r"(r0),"=r"(r1),"=r"(r2),"=r"(r3) : "r"(a))
#define LDSM4T(r0,r1,r2,r3,a) asm volatile("ldmatrix.sync.aligned.m8n8.x4.trans.shared.b16 {%0,%1,%2,%3},[%4];" \
    : "=r"(r0),"=r"(r1),"=r"(r2),"=r"(r3) : "r"(a))
#define MMA(d,a,b) asm volatile( \
    "mma.sync.aligned.m16n8k16.row.col.f32.f16.f16.f32 {%0,%1,%2,%3},{%4,%5,%6,%7},{%8,%9},{%0,%1,%2,%3};" \
    : "+f"((d)[0]),"+f"((d)[1]),"+f"((d)[2]),"+f"((d)[3]) \
    : "r"((a)[0]),"r"((a)[1]),"r"((a)[2]),"r"((a)[3]),"r"((b)[0]),"r"((b)[1]))
#define CPA16(dst, src)  asm volatile("cp.async.cg.shared.global [%0],[%1],16;" :: "r"(dst), "l"(src))
#define CPA_COMMIT()     asm volatile("cp.async.commit_group;" ::: "memory")
#define CPA_WAIT0()      asm volatile("cp.async.wait_group 0;" ::: "memory")

static __device__ __forceinline__ uint32_t h2pack(__half a, __half b) {
    return (uint32_t)__half_as_ushort(b) << 16 | (uint32_t)__half_as_ushort(a);
}
static __device__ __forceinline__ void split2(float x, float y, uint32_t& hi, uint32_t& lo) {
    __half hx = __float2half_rn(x), hy = __float2half_rn(y);
    __half lx = __float2half_rn(x - __half2float(hx));
    __half ly = __float2half_rn(y - __half2float(hy));
    hi = h2pack(hx, hy);
    lo = h2pack(lx, ly);
}
static __device__ __forceinline__ void dfrag_to_afrag(const float D[8][4], float s0, float s1,
                                                      uint32_t Ah[4][4], uint32_t Al[4][4]) {
    #pragma unroll
    for (int ks = 0; ks < 4; ++ks) {
        split2(D[2*ks][0]*s0,   D[2*ks][1]*s0,   Ah[ks][0], Al[ks][0]);
        split2(D[2*ks][2]*s1,   D[2*ks][3]*s1,   Ah[ks][1], Al[ks][1]);
        split2(D[2*ks+1][0]*s0, D[2*ks+1][1]*s0, Ah[ks][2], Al[ks][2]);
        split2(D[2*ks+1][2]*s1, D[2*ks+1][3]*s1, Ah[ks][3], Al[ks][3]);
    }
}
static __device__ __forceinline__ void dfrag_to_afrag_hi(const float D[8][4], uint32_t Ah[4][4]) {
    #pragma unroll
    for (int ks = 0; ks < 4; ++ks) {
        Ah[ks][0] = h2pack(__float2half_rn(D[2*ks][0]),   __float2half_rn(D[2*ks][1]));
        Ah[ks][1] = h2pack(__float2half_rn(D[2*ks][2]),   __float2half_rn(D[2*ks][3]));
        Ah[ks][2] = h2pack(__float2half_rn(D[2*ks+1][0]), __float2half_rn(D[2*ks+1][1]));
        Ah[ks][3] = h2pack(__float2half_rn(D[2*ks+1][2]), __float2half_rn(D[2*ks+1][3]));
    }
}

#define L2E 1.4426950408889634f

// ONE prep kernel, grid 288 x 256
__global__ void prep(const float* __restrict__ Wq, const float* __restrict__ bq,
                     const float* __restrict__ Wk, const float* __restrict__ nb,
                     const float* __restrict__ Wv) {
    int b = blockIdx.x;
    if (b < 256) {
        int idx = b * 256 + threadIdx.x;          // 65536
        int row = idx >> 6, d = idx & 63;
        int t = row >> 6, j = row & 63;
        float v = nb[idx];
        __half h = __float2half_rn(v);
        __half l = __float2half_rn(v - __half2float(h));
        g_nb[t*9216 + j*STRD + d] = h;
        g_nb[t*9216 + 4608 + j*STRD + d] = l;
    } else if (b < 272) {
        int idx = (b - 256) * 256 + threadIdx.x;  // 4096
        int j = idx >> 6, d = idx & 63;
        float s = 0.f;
        #pragma unroll 8
        for (int t = 0; t < 64; ++t) s += Wk[t*64 + j] * Wq[t*64 + d];
        s *= L2E;                                  // fold log2(e): logits in log2 domain
        __half h = __float2half_rn(s);
        __half l = __float2half_rn(s - __half2float(h));
        g_wA[j*STRD + d] = h;
        g_wA[4608 + j*STRD + d] = l;
        if (b == 256 && threadIdx.x < 64) {
            int jj = threadIdx.x;
            float bb = 0.f;
            #pragma unroll 8
            for (int t = 0; t < 64; ++t) bb += Wk[t*64 + jj] * bq[t];
            g_bp[jj] = bb * L2E;
        }
    } else {
        int idx = (b - 272) * 256 + threadIdx.x;  // 4096
        int o = idx >> 6, e = idx & 63;
        float v = Wv[idx];
        __half h = __float2half_rn(v);
        __half l = __float2half_rn(v - __half2float(h));
        g_wV[o*STRD + e] = h;
        g_wV[4608 + o*STRD + e] = l;
    }
}

__global__ void __launch_bounds__(NTHR, 4)
gat_kernel(const float* __restrict__ x, const float* __restrict__ bv,
           float* __restrict__ out, int N) {
    extern __shared__ char sm[];
    const uint32_t su = smem_u32(sm);
    const int tid = threadIdx.x, lane = tid & 31, wid = tid >> 5;   // 4 warps
    const int g = lane >> 2, tg = lane & 3;
    const int m0 = wid * 16;
    const int n0 = blockIdx.x * BR;
    float* bias = (float*)(sm + BIAS_B);

    const int rN = ((lane >> 4) & 1) * 8 + (lane & 7);
    const int cN = ((lane >> 3) & 1) * 8;
    const int rT = ((lane >> 3) & 1) * 8 + (lane & 7);
    const int cT = ((lane >> 4) & 1) * 8;

    // ---- start tile-0 + A-image copies immediately ----
    {
        const char* s0 = (const char*)g_nb;
        const char* sa = (const char*)g_wA;
        for (int i = tid; i < 1152; i += NTHR) {
            CPA16(su + i*16, s0 + i*16);
            CPA16(su + WH_B + i*16, sa + i*16);
        }
        CPA_COMMIT();
    }
    if (tid < 64) bias[tid] = g_bp[tid];

    // ---- x fragments straight from global ----
    uint32_t Xh[4][4], Xl[4][4];
    {
        int r0 = n0 + m0 + g, r1 = r0 + 8;
        #pragma unroll
        for (int q = 0; q < 8; ++q) {
            int c = 2*tg + 8*q;
            float2 v0 = make_float2(0.f, 0.f), v1 = make_float2(0.f, 0.f);
            if (r0 < N) v0 = *(const float2*)&x[(size_t)r0*DI + c];
            if (r1 < N) v1 = *(const float2*)&x[(size_t)r1*DI + c];
            int ks = q >> 1;
            if ((q & 1) == 0) {
                split2(v0.x, v0.y, Xh[ks][0], Xl[ks][0]);
                split2(v1.x, v1.y, Xh[ks][1], Xl[ks][1]);
            } else {
                split2(v0.x, v0.y, Xh[ks][2], Xl[ks][2]);
                split2(v1.x, v1.y, Xh[ks][3], Xl[ks][3]);
            }
        }
    }
    CPA_WAIT0();
    __syncthreads();

    // ---- GEMM0: p = (x @ A^T + bp) * log2e (3-pass, precision-critical) ----
    float D[8][4];
    #pragma unroll
    for (int b = 0; b < 8; ++b) {
        D[b][0] = bias[8*b + 2*tg]; D[b][1] = bias[8*b + 2*tg + 1];
        D[b][2] = D[b][0];          D[b][3] = D[b][1];
    }
    #pragma unroll
    for (int ks = 0; ks < 4; ++ks)
        #pragma unroll
        for (int P = 0; P < 4; ++P) {
            uint32_t off = ((16*P + rN)*STRD + 16*ks + cN) * 2;
            uint32_t bh[4], bl[4];
            LDSM4(bh[0], bh[1], bh[2], bh[3], su + WH_B + off);
            LDSM4(bl[0], bl[1], bl[2], bl[3], su + WH_B + 9216 + off);
            MMA(D[2*P],   Xh[ks], bh);     MMA(D[2*P],   Xl[ks], bh);     MMA(D[2*P],   Xh[ks], bl);
            MMA(D[2*P+1], Xh[ks], bh+2);   MMA(D[2*P+1], Xl[ks], bh+2);   MMA(D[2*P+1], Xh[ks], bl+2);
        }
    uint32_t Ph[4][4], Pl[4][4];
    dfrag_to_afrag(D, 1.f, 1.f, Ph, Pl);

    // ---- flash loop (double-buffered nb stages) ----
    float ag[8][4];
    #pragma unroll
    for (int b = 0; b < 8; ++b)
        #pragma unroll
        for (int u = 0; u < 4; ++u) ag[b][u] = 0.f;
    float mr0 = -1e30f, mr1 = -1e30f, lr0 = 0.f, lr1 = 0.f;  // lr: per-lane partials

    for (int t = 0; t < 16; ++t) {
        CPA_WAIT0();
        __syncthreads();
        if (t + 1 < 16) {
            uint32_t dst = su + ((t + 1) & 1) * STG_BYTES;
            const char* src = (const char*)g_nb + (t + 1) * STG_BYTES;
            for (int i = tid; i < 1152; i += NTHR) CPA16(dst + i*16, src + i*16);
        }
        if (t == 0) {   // Wv image into weight region freed by GEMM0
            const char* sv = (const char*)g_wV;
            for (int i = tid; i < 1152; i += NTHR) CPA16(su + WH_B + i*16, sv + i*16);
        }
        CPA_COMMIT();
        const uint32_t sH = su + (t & 1) * STG_BYTES;
        const uint32_t sL = sH + 9216;

        // GEMM1: S = p @ nb^T (3-pass; logits in log2 domain)
        float S[8][4];
        #pragma unroll
        for (int b = 0; b < 8; ++b)
            #pragma unroll
            for (int u = 0; u < 4; ++u) S[b][u] = 0.f;
        #pragma unroll
        for (int ks = 0; ks < 4; ++ks)
            #pragma unroll
            for (int P = 0; P < 4; ++P) {
                uint32_t off = ((16*P + rN)*STRD + 16*ks + cN) * 2;
                uint32_t bh[4], bl[4];
                LDSM4(bh[0], bh[1], bh[2], bh[3], sH + off);
                LDSM4(bl[0], bl[1], bl[2], bl[3], sL + off);
                MMA(S[2*P],   Ph[ks], bh);   MMA(S[2*P],   Pl[ks], bh);   MMA(S[2*P],   Ph[ks], bl);
                MMA(S[2*P+1], Ph[ks], bh+2); MMA(S[2*P+1], Pl[ks], bh+2); MMA(S[2*P+1], Ph[ks], bl+2);
            }

        // online softmax in log2 domain (max reduced across 4 lanes; sum stays per-lane)
        float mx0 = -1e30f, mx1 = -1e30f;
        #pragma unroll
        for (int b = 0; b < 8; ++b) {
            mx0 = fmaxf(mx0, fmaxf(S[b][0], S[b][1]));
            mx1 = fmaxf(mx1, fmaxf(S[b][2], S[b][3]));
        }
        mx0 = fmaxf(mx0, __shfl_xor_sync(0xFFFFFFFFu, mx0, 1));
        mx0 = fmaxf(mx0, __shfl_xor_sync(0xFFFFFFFFu, mx0, 2));
        mx1 = fmaxf(mx1, __shfl_xor_sync(0xFFFFFFFFu, mx1, 1));
        mx1 = fmaxf(mx1, __shfl_xor_sync(0xFFFFFFFFu, mx1, 2));
        float mn0 = fmaxf(mr0, mx0), mn1 = fmaxf(mr1, mx1);
        float sc0 = ex2f(mr0 - mn0), sc1 = ex2f(mr1 - mn1);
        mr0 = mn0; mr1 = mn1;
        float s0 = 0.f, s1 = 0.f;
        #pragma unroll
        for (int b = 0; b < 8; ++b) {
            S[b][0] = ex2f(S[b][0] - mn0); s0 += S[b][0];
            S[b][1] = ex2f(S[b][1] - mn0); s0 += S[b][1];
            S[b][2] = ex2f(S[b][2] - mn1); s1 += S[b][2];
            S[b][3] = ex2f(S[b][3] - mn1); s1 += S[b][3];
        }
        lr0 = lr0 * sc0 + s0;     // per-lane partial (sc identical across the 4 lanes)
        lr1 = lr1 * sc1 + s1;

        uint32_t Th[4][4];
        dfrag_to_afrag_hi(S, Th);
        #pragma unroll
        for (int b = 0; b < 8; ++b) {
            ag[b][0] *= sc0; ag[b][1] *= sc0;
            ag[b][2] *= sc1; ag[b][3] *= sc1;
        }

        // GEMM2: ag += attn @ nb (single pass: attn-hi x nb-hi)
        #pragma unroll
        for (int ks = 0; ks < 4; ++ks)
            #pragma unroll
            for (int P = 0; P < 4; ++P) {
                uint32_t off = ((16*ks + rT)*STRD + 16*P + cT) * 2;
                uint32_t bh[4];
                LDSM4T(bh[0], bh[1], bh[2], bh[3], sH + off);
                MMA(ag[2*P],   Th[ks], bh);
                MMA(ag[2*P+1], Th[ks], bh+2);
            }
    }

    // ---- finalize row sums across the 4 lanes sharing each row ----
    lr0 += __shfl_xor_sync(0xFFFFFFFFu, lr0, 1);
    lr0 += __shfl_xor_sync(0xFFFFFFFFu, lr0, 2);
    lr1 += __shfl_xor_sync(0xFFFFFFFFu, lr1, 1);
    lr1 += __shfl_xor_sync(0xFFFFFFFFu, lr1, 2);

    // ---- epilogue: normalize -> A-frags; GEMM3 (3-pass); store ----
    float inv0 = 1.0f / lr0, inv1 = 1.0f / lr1;
    uint32_t Gh[4][4], Gl[4][4];
    dfrag_to_afrag(ag, inv0, inv1, Gh, Gl);
    if (tid < 64) bias[tid] = bv[tid];
    __syncthreads();
    float O[8][4];
    #pragma unroll
    for (int b = 0; b < 8; ++b) {
        O[b][0] = bias[8*b + 2*tg]; O[b][1] = bias[8*b + 2*tg + 1];
        O[b][2] = O[b][0];          O[b][3] = O[b][1];
    }
    #pragma unroll
    for (int ks = 0; ks < 4; ++ks)
        #pragma unroll
        for (int P = 0; P < 4; ++P) {
            uint32_t off = ((16*P + rN)*STRD + 16*ks + cN) * 2;
            uint32_t bh[4], bl[4];
            LDSM4(bh[0], bh[1], bh[2], bh[3], su + WH_B + off);
            LDSM4(bl[0], bl[1], bl[2], bl[3], su + WH_B + 9216 + off);
            MMA(O[2*P],   Gh[ks], bh);   MMA(O[2*P],   Gl[ks], bh);   MMA(O[2*P],   Gh[ks], bl);
            MMA(O[2*P+1], Gh[ks], bh+2); MMA(O[2*P+1], Gl[ks], bh+2); MMA(O[2*P+1], Gh[ks], bl+2);
        }
    #pragma unroll
    for (int b = 0; b < 8; ++b) {
        int col = 8*b + 2*tg;
        int row0 = n0 + m0 + g;
        if (row0 < N) *(float2*)&out[(size_t)row0*DI + col] = make_float2(O[b][0], O[b][1]);
        int row1 = row0 + 8;
        if (row1 < N) *(float2*)&out[(size_t)row1*DI + col] = make_float2(O[b][2], O[b][3]);
    }
}

extern "C" void kernel_launch(void* const* d_in, const int* in_sizes, int n_in,
                              void* d_out, int out_size) {
    const float* x  = (const float*)d_in[0];
    const float* nb = (const float*)d_in[1];
    const float* Wq = (const float*)d_in[2];
    const float* bq = (const float*)d_in[3];
    const float* Wk = (const float*)d_in[4];
    // d_in[5] = bk drops out of softmax
    const float* Wv = (const float*)d_in[6];
    const float* bv = (const float*)d_in[7];
    float* out = (float*)d_out;
    const int N = in_sizes[0] / DI;
    cudaFuncSetAttribute(gat_kernel, cudaFuncAttributeMaxDynamicSharedMemorySize, SM_BYTES);
    prep<<<288, 256>>>(Wq, bq, Wk, nb, Wv);
    gat_kernel<<<(N + BR - 1) / BR, NTHR, SM_BYTES>>>(x, bv, out, N);
}